// round 11
// baseline (speedup 1.0000x reference)
#include <cuda_runtime.h>
#include <cuda_bf16.h>
#include <math.h>
#include <stdint.h>

#define NB   64
#define TT   64
#define VV   25
#define DIMC 384
#define HH   6
#define HD   64
#define TV   1600                 // T*V
#define SL   39321600             // N*T*H*HD*V  (per-slot scratch size)
#define NSTRIDE 614400u           // T*H*HD*V    (per-n stride within a slot)
#define XPITCH 1664               // padded TV for cp.async (multiple of 128)

// Scratch: slots 0..4 = K, V, Q, EK, EQ, each [N,T,H,V,HD] fp32 (v-major inner)
__device__ float g_proj[5u * SL];
// Pre-split GEMM operands (bf16 hi/lo)
__device__ __nv_bfloat16 g_whi[1920 * 384];
__device__ __nv_bfloat16 g_wlo[1920 * 384];
__device__ __nv_bfloat16 g_xhi[2u * NB * DIMC * XPITCH];
__device__ __nv_bfloat16 g_xlo[2u * NB * DIMC * XPITCH];

// ---------------- helpers ----------------
__device__ __forceinline__ uint32_t smem_u32(const void* p) {
    uint32_t a;
    asm("{ .reg .u64 t; cvta.to.shared.u64 t, %1; cvt.u32.u64 %0, t; }"
        : "=r"(a) : "l"(p));
    return a;
}
__device__ __forceinline__ void split4(float4 v, uint2& h, uint2& l) {
    __nv_bfloat162 h0 = __floats2bfloat162_rn(v.x, v.y);
    __nv_bfloat162 h1 = __floats2bfloat162_rn(v.z, v.w);
    float2 f0 = __bfloat1622float2(h0);
    float2 f1 = __bfloat1622float2(h1);
    __nv_bfloat162 l0 = __floats2bfloat162_rn(v.x - f0.x, v.y - f0.y);
    __nv_bfloat162 l1 = __floats2bfloat162_rn(v.z - f1.x, v.w - f1.y);
    h = make_uint2(*(uint32_t*)&h0, *(uint32_t*)&h1);
    l = make_uint2(*(uint32_t*)&l0, *(uint32_t*)&l1);
}
__device__ __forceinline__ void ldsm4(uint32_t addr, uint32_t* r) {
    asm volatile("ldmatrix.sync.aligned.m8n8.x4.shared.b16 {%0,%1,%2,%3}, [%4];"
                 : "=r"(r[0]), "=r"(r[1]), "=r"(r[2]), "=r"(r[3]) : "r"(addr));
}
__device__ __forceinline__ void ldsm4t(uint32_t addr, uint32_t* r) {
    asm volatile("ldmatrix.sync.aligned.m8n8.x4.trans.shared.b16 {%0,%1,%2,%3}, [%4];"
                 : "=r"(r[0]), "=r"(r[1]), "=r"(r[2]), "=r"(r[3]) : "r"(addr));
}
__device__ __forceinline__ void mma_bf16(float* c, const uint32_t* a, const uint32_t* b) {
    asm volatile("mma.sync.aligned.m16n8k16.row.col.f32.bf16.bf16.f32 "
                 "{%0,%1,%2,%3}, {%4,%5,%6,%7}, {%8,%9}, {%0,%1,%2,%3};"
                 : "+f"(c[0]), "+f"(c[1]), "+f"(c[2]), "+f"(c[3])
                 : "r"(a[0]), "r"(a[1]), "r"(a[2]), "r"(a[3]), "r"(b[0]), "r"(b[1]));
}
__device__ __forceinline__ void cp16(uint32_t dst, const void* src) {
    asm volatile("cp.async.cg.shared.global [%0], [%1], 16;" :: "r"(dst), "l"(src));
}
__device__ __forceinline__ void cp_commit() {
    asm volatile("cp.async.commit_group;" ::: "memory");
}
template <int N>
__device__ __forceinline__ void cp_wait() {
    asm volatile("cp.async.wait_group %0;" :: "n"(N) : "memory");
}

// =====================================================================
// Pre-split kernels: fp32 -> bf16 hi/lo
// =====================================================================
__global__ __launch_bounds__(256) void presplit_w(
    const float* __restrict__ kv_w, const float* __restrict__ q_w,
    const float* __restrict__ e_kv_w, const float* __restrict__ e_q_w)
{
    int id = blockIdx.x * 256 + threadIdx.x;
    if (id >= 1920 * 384 / 4) return;
    int idx4 = id * 4;
    int r = idx4 / 384, c = idx4 % 384;
    const float* src;
    if      (r < 768)  src = kv_w   + (size_t)r * 384 + c;
    else if (r < 1152) src = q_w    + (size_t)(r - 768) * 384 + c;
    else if (r < 1536) src = e_kv_w + (size_t)(r - 1152) * 384 + c;
    else               src = e_q_w  + (size_t)(r - 1536) * 384 + c;
    float4 v = *(const float4*)src;
    uint2 h, l; split4(v, h, l);
    *(uint2*)&g_whi[idx4] = h;
    *(uint2*)&g_wlo[idx4] = l;
}

__global__ __launch_bounds__(256) void presplit_x(
    const float* __restrict__ x, const float* __restrict__ e)
{
    const int k = blockIdx.x, n = blockIdx.y, path = blockIdx.z;
    const float* src = (path ? e : x) + ((size_t)n * DIMC + k) * TV;
    size_t dst = ((size_t)(path * NB + n) * DIMC + k) * XPITCH;
    for (int l4 = threadIdx.x; l4 < XPITCH / 4; l4 += 256) {
        int f = l4 * 4;
        float4 v = (f < TV) ? *(const float4*)(src + f) : make_float4(0.f, 0.f, 0.f, 0.f);
        uint2 h, l; split4(v, h, l);
        *(uint2*)&g_xhi[dst + f] = h;
        *(uint2*)&g_xlo[dst + f] = l;
    }
}

// =====================================================================
// Projection GEMM via mma.sync bf16 (unchanged from R9).
// =====================================================================
#define A_PITCH 80
#define B_PITCH 272
#define A_BYTES (128 * A_PITCH)
#define B_BYTES (32 * B_PITCH)
#define STAGE_BYTES (2 * A_BYTES + 2 * B_BYTES)
#define DYN_BYTES (3 * STAGE_BYTES)

__global__ __launch_bounds__(256, 2)
void proj_mma()
{
    const int nt  = blockIdx.x;
    const int mt  = blockIdx.y;
    const int n   = blockIdx.z;
    const int tid = threadIdx.x;
    const int lane = tid & 31;
    const int w    = tid >> 5;
    const int wm   = w & 3;
    const int wn   = w >> 2;

    extern __shared__ char smem[];
    const uint32_t smem_b = smem_u32(smem);

    const int path = (mt >= 9);
    const int o_origin = (mt < 12) ? ((mt < 9) ? mt * 128 : (mt - 9) * 128)
                                   : (384 + (mt - 12) * 128);
    const int wrow0 = mt * 128;
    const int p0 = nt * 128;

    const __nv_bfloat16* Xhi = g_xhi + ((size_t)(path * NB + n) * DIMC) * XPITCH;
    const __nv_bfloat16* Xlo = g_xlo + ((size_t)(path * NB + n) * DIMC) * XPITCH;

    const int a_row0 = (tid * 2) >> 2;
    const int a_s0   = (tid * 2) & 3;
    const int b_row0 = (tid * 2) >> 4;
    const int b_s0   = (tid * 2) & 15;

    const uint32_t aoff = (uint32_t)((wm * 32 + (lane & 15)) * A_PITCH + (lane >> 4) * 16);
    const uint32_t boff = (uint32_t)((lane & 15) * B_PITCH + (wn * 64 + (lane >> 4) * 8) * 2);

    float acc[16][4];
#pragma unroll
    for (int i = 0; i < 16; i++)
#pragma unroll
        for (int j = 0; j < 4; j++) acc[i][j] = 0.f;

    auto issue = [&](int c) {
        const int k0 = c * 32;
        const uint32_t st = smem_b + (uint32_t)((c % 3) * STAGE_BYTES);
#pragma unroll
        for (int i = 0; i < 2; i++) {
            int ar = a_row0;
            int as = (a_s0 + i) & 3;
            if (a_s0 + i >= 4) { ar = a_row0 + 1; }
            size_t asrc = (size_t)(wrow0 + ar) * 384 + k0 + as * 8;
            uint32_t adst = st + (uint32_t)(ar * A_PITCH + as * 16);
            cp16(adst, g_whi + asrc);
            cp16(adst + A_BYTES, g_wlo + asrc);
            int br = b_row0 + ((b_s0 + i) >= 16 ? 1 : 0);
            int bs = (b_s0 + i) & 15;
            size_t bsrc = (size_t)(k0 + br) * XPITCH + p0 + bs * 8;
            uint32_t bdst = st + (uint32_t)(2 * A_BYTES + br * B_PITCH + bs * 16);
            cp16(bdst, Xhi + bsrc);
            cp16(bdst + B_BYTES, Xlo + bsrc);
        }
        cp_commit();
    };

    issue(0);
    issue(1);

    for (int c = 0; c < 12; ++c) {
        if (c < 11) cp_wait<1>(); else cp_wait<0>();
        __syncthreads();
        if (c < 10) issue(c + 2);

        const uint32_t stage = smem_b + (uint32_t)((c % 3) * STAGE_BYTES);
        const uint32_t aHi = stage + aoff;
        const uint32_t aLo = aHi + A_BYTES;
        const uint32_t bHi = stage + 2 * A_BYTES + boff;
        const uint32_t bLo = bHi + B_BYTES;
#pragma unroll
        for (int s = 0; s < 2; s++) {
            uint32_t Ah[2][4], Al[2][4];
#pragma unroll
            for (int m = 0; m < 2; m++) {
                ldsm4(aHi + m * 16 * A_PITCH + s * 32, Ah[m]);
                ldsm4(aLo + m * 16 * A_PITCH + s * 32, Al[m]);
            }
            uint32_t Bh[4][4], Bl[4][4];
#pragma unroll
            for (int g = 0; g < 4; g++) {
                ldsm4t(bHi + s * 16 * B_PITCH + g * 32, Bh[g]);
                ldsm4t(bLo + s * 16 * B_PITCH + g * 32, Bl[g]);
            }
#pragma unroll
            for (int m = 0; m < 2; m++)
#pragma unroll
                for (int g = 0; g < 4; g++)
#pragma unroll
                    for (int half = 0; half < 2; half++) {
                        float* cc = acc[m * 8 + g * 2 + half];
                        mma_bf16(cc, Ah[m], &Bh[g][half * 2]);
                        mma_bf16(cc, Ah[m], &Bl[g][half * 2]);
                        mma_bf16(cc, Al[m], &Bh[g][half * 2]);
                    }
        }
        __syncthreads();
    }

    const int g   = lane >> 2;
    const int tig = lane & 3;
#pragma unroll
    for (int m = 0; m < 2; m++) {
#pragma unroll
        for (int ntile = 0; ntile < 8; ntile++) {
#pragma unroll
            for (int j = 0; j < 4; j++) {
                int o_g = o_origin + wm * 32 + m * 16 + g + (j >> 1) * 8;
                uint32_t p = (uint32_t)(p0 + wn * 64 + ntile * 8 + tig * 2 + (j & 1));
                if (p < TV) {
                    int cdiv = o_g / 384;
                    int slot = cdiv + (path ? 3 : 0);
                    int rem  = o_g - cdiv * 384;
                    int hh = rem >> 6, dd = rem & 63;
                    uint32_t t = (p * 5243u) >> 17;
                    uint32_t v = p - t * 25u;
                    uint32_t addr = (uint32_t)slot * (uint32_t)SL + (uint32_t)n * NSTRIDE
                                  + t * 9600u + (uint32_t)hh * 1600u + v * 64u + (uint32_t)dd;
                    g_proj[addr] = acc[m * 8 + ntile][j];
                }
            }
        }
    }
}

// =====================================================================
// Kernel B: attention with tensor-core scores + fused grouped projection.
// One block (128 threads) per (n,t,h).
// smem map (floats): region A [0..8192) = bf16-split score operands
//   (8 matrices, 32 rows x 128B, XOR-16B swizzle); later reused:
//   OXO=0 (25x68), OW=1792 (64x64)
// OS=8192 (25x28), OD=8892, OQR=9592 .. 10292
// =====================================================================
#define QHI_B  0
#define QLO_B  4096
#define EQHI_B 8192
#define EQLO_B 12288
#define KEHI_B 16384
#define KELO_B 20480
#define EKHI_B 24576
#define EKLO_B 28672
#define OS_F   8192
#define OD_F   8892
#define OQR_F  9592

__global__ __launch_bounds__(128) void attn_kernel(
    const float* __restrict__ rpe, const float* __restrict__ outer,
    const float* __restrict__ alpha_p, const float* __restrict__ beta_p,
    const float* __restrict__ proj_w, const float* __restrict__ proj_b,
    const int* __restrict__ hops, int nh,
    float* __restrict__ xo_out, float* __restrict__ eo_out)
{
    const int h = blockIdx.x, t = blockIdx.y, n = blockIdx.z;
    const int tid = threadIdx.x;
    const int lane = tid & 31;
    const int w = tid >> 5;

    __shared__ __align__(16) float sm[10292];
    __shared__ unsigned char shops[640];
    char* smA = (char*)sm;
    const uint32_t smA_u = smem_u32(sm);

    const int P = 68;
    const int OXO = 0;
    const int OW  = 1792;

    const size_t base = (((size_t)n * TT + t) * HH + h) * (size_t)(HD * VV);

    // ---- phase 0: zero pad rows (25..31 of all 8 matrices) + load/split ----
    for (int z = tid; z < 448; z += 128) {
        int r = z >> 3, c = z & 7;
        int mtx = r / 7, row = 25 + (r % 7);
        *(float4*)(smA + mtx * 4096 + row * 128 + c * 16) =
            make_float4(0.f, 0.f, 0.f, 0.f);
    }
    for (int l4 = tid; l4 < 400; l4 += 128) {
        int f = l4 * 4;
        int v = f >> 6, d = f & 63;
        float4 k4  = *(const float4*)&g_proj[0 * (size_t)SL + base + f];
        float4 q4  = *(const float4*)&g_proj[2 * (size_t)SL + base + f];
        float4 ek4 = *(const float4*)&g_proj[3 * (size_t)SL + base + f];
        float4 eq4 = *(const float4*)&g_proj[4 * (size_t)SL + base + f];
        float4 ke4 = make_float4(k4.x + ek4.x, k4.y + ek4.y, k4.z + ek4.z, k4.w + ek4.w);
        int c16 = d >> 3;
        uint32_t off = (uint32_t)(v * 128 + ((c16 ^ (v & 7)) * 16) + ((d & 7) ? 8 : 0));
        uint2 hh, ll;
        split4(q4, hh, ll);
        *(uint2*)(smA + QHI_B + off) = hh;  *(uint2*)(smA + QLO_B + off) = ll;
        split4(eq4, hh, ll);
        *(uint2*)(smA + EQHI_B + off) = hh; *(uint2*)(smA + EQLO_B + off) = ll;
        split4(ke4, hh, ll);
        *(uint2*)(smA + KEHI_B + off) = hh; *(uint2*)(smA + KELO_B + off) = ll;
        split4(ek4, hh, ll);
        *(uint2*)(smA + EKHI_B + off) = hh; *(uint2*)(smA + EKLO_B + off) = ll;
    }
    for (int l = tid; l < 625; l += 128) shops[l] = (unsigned char)hops[l];
    __syncthreads();

    // ---- phase 1: qR[i][hop] = q_i . rpe[hop]  (q from gmem, L1-hit) ----
    for (int l = tid; l < 25 * nh; l += 128) {
        int i = l / nh, hp = l % nh;
        const float* qi = &g_proj[2 * (size_t)SL + base + i * 64];
        const float* rr = rpe + (size_t)hp * DIMC + h * HD;
        float acc = 0.f;
#pragma unroll
        for (int d = 0; d < 64; d += 4) {
            float4 q4 = *(const float4*)(qi + d);
            float4 r4 = *(const float4*)(rr + d);
            acc += q4.x * r4.x + q4.y * r4.y + q4.z * r4.z + q4.w * r4.w;
        }
        sm[OQR_F + i * 28 + hp] = acc;
    }
    __syncthreads();

    // ---- phase 2: scores via mma. warp w: rows (w&1)*16.., cols (w>>1)*16.. ----
    {
        const int mt = w & 1;
        const int nb = (w >> 1) * 16;
        const int arow = mt * 16 + (lane & 15);
        const int brow = nb + (lane & 15);
        float accS[2][4], accD[2][4];
#pragma unroll
        for (int i = 0; i < 2; i++)
#pragma unroll
            for (int j = 0; j < 4; j++) { accS[i][j] = 0.f; accD[i][j] = 0.f; }

#pragma unroll
        for (int s = 0; s < 4; s++) {
            uint32_t abyte = (uint32_t)(arow * 128 + (((s * 2 + (lane >> 4)) ^ (arow & 7)) * 16));
            uint32_t bbyte = (uint32_t)(brow * 128 + (((s * 2 + (lane >> 4)) ^ (brow & 7)) * 16));
            uint32_t qh[4], ql[4], eqh[4], eql[4], keh[4], kel[4], ekh[4], ekl[4];
            ldsm4(smA_u + QHI_B  + abyte, qh);
            ldsm4(smA_u + QLO_B  + abyte, ql);
            ldsm4(smA_u + EQHI_B + abyte, eqh);
            ldsm4(smA_u + EQLO_B + abyte, eql);
            ldsm4(smA_u + KEHI_B + bbyte, keh);
            ldsm4(smA_u + KELO_B + bbyte, kel);
            ldsm4(smA_u + EKHI_B + bbyte, ekh);
            ldsm4(smA_u + EKLO_B + bbyte, ekl);
#pragma unroll
            for (int ns = 0; ns < 2; ns++) {
                uint32_t bKEh[2] = {keh[ns], keh[ns + 2]};
                uint32_t bKEl[2] = {kel[ns], kel[ns + 2]};
                uint32_t bEKh[2] = {ekh[ns], ekh[ns + 2]};
                uint32_t bEKl[2] = {ekl[ns], ekl[ns + 2]};
                mma_bf16(accS[ns], qh, bKEh);
                mma_bf16(accS[ns], qh, bKEl);
                mma_bf16(accS[ns], ql, bKEh);
                mma_bf16(accD[ns], eqh, bEKh);
                mma_bf16(accD[ns], eqh, bEKl);
                mma_bf16(accD[ns], eql, bEKh);
            }
        }
        // epilogue: S = G1 + G2 + b(rpe/hops), D = G2
#pragma unroll
        for (int ns = 0; ns < 2; ns++) {
#pragma unroll
            for (int j = 0; j < 4; j++) {
                int row = mt * 16 + (lane >> 2) + (j >> 1) * 8;
                int col = nb + ns * 8 + (lane & 3) * 2 + (j & 1);
                if (row < 25 && col < 25) {
                    float g2 = accD[ns][j];
                    float b = sm[OQR_F + row * 28 + shops[row * 25 + col]];
                    sm[OS_F + row * 28 + col] = accS[ns][j] + g2 + b;
                    sm[OD_F + row * 28 + col] = g2;
                }
            }
        }
    }
    __syncthreads();

    const float alpha = __ldg(alpha_p);
    const float beta  = __ldg(beta_p);
    const float scale = 0.125f;

    // ---- phase 3: softmax (50 rows), fold alpha/outer/beta ----
    if (tid < 50) {
        int i = tid % 25;
        float* row = &sm[(tid < 25 ? OS_F : OD_F) + i * 28];
        float m = -1e30f;
#pragma unroll
        for (int j = 0; j < 25; j++) m = fmaxf(m, row[j]);
        float ebuf[25];
        float s = 0.f;
#pragma unroll
        for (int j = 0; j < 25; j++) { float v = expf((row[j] - m) * scale); ebuf[j] = v; s += v; }
        float inv = 1.f / s;
        if (tid < 25) {
            const float* orow = outer + (size_t)h * 625 + i * 25;
#pragma unroll
            for (int j = 0; j < 25; j++)
                row[j] = alpha * (ebuf[j] * inv) + __ldg(orow + j);
        } else {
#pragma unroll
            for (int j = 0; j < 25; j++)
                row[j] = beta * (ebuf[j] * inv);
        }
    }
    __syncthreads();

    // ---- phase 4: AV (V from gmem slot 1, L1-cached) ----
    if (tid < 80) {
        int ig = tid / 16;
        int dg = tid % 16;
        float aX[5][4], aE[5][4];
#pragma unroll
        for (int ii = 0; ii < 5; ii++)
#pragma unroll
            for (int dd = 0; dd < 4; dd++) { aX[ii][dd] = 0.f; aE[ii][dd] = 0.f; }
#pragma unroll
        for (int j = 0; j < 25; j++) {
            float4 v4 = __ldg((const float4*)&g_proj[1 * (size_t)SL + base + j * 64 + dg * 4]);
#pragma unroll
            for (int ii = 0; ii < 5; ii++) {
                float a  = sm[OS_F + (ig * 5 + ii) * 28 + j];
                float dc = sm[OD_F + (ig * 5 + ii) * 28 + j];
                aX[ii][0] += a * v4.x;  aX[ii][1] += a * v4.y;
                aX[ii][2] += a * v4.z;  aX[ii][3] += a * v4.w;
                aE[ii][0] += dc * v4.x; aE[ii][1] += dc * v4.y;
                aE[ii][2] += dc * v4.z; aE[ii][3] += dc * v4.w;
            }
        }
#pragma unroll
        for (int ii = 0; ii < 5; ii++) {
            int i = ig * 5 + ii;
#pragma unroll
            for (int dd = 0; dd < 4; dd++) {
                int d = dg * 4 + dd;
                eo_out[(((size_t)n * DIMC + h * HD + d) * TT + t) * VV + i] = aE[ii][dd];
                sm[OXO + i * P + d] = aX[ii][dd];
            }
        }
    }
    // proj weights -> smem (region A reuse, disjoint from OXO)
    for (int l4 = tid; l4 < 1024; l4 += 128)
        *(float4*)&sm[OW + l4 * 4] = *(const float4*)&proj_w[(size_t)h * 4096 + l4 * 4];
    __syncthreads();

    // ---- phase 5: grouped projection ----
    if (tid < 80) {
        int ig = tid / 16;
        int og = tid % 16;
        float acc[5][4];
#pragma unroll
        for (int ii = 0; ii < 5; ii++)
#pragma unroll
            for (int oo = 0; oo < 4; oo++) acc[ii][oo] = 0.f;
#pragma unroll
        for (int c = 0; c < 64; c += 4) {
            float4 w4[4];
#pragma unroll
            for (int oo = 0; oo < 4; oo++)
                w4[oo] = *(const float4*)&sm[OW + (og * 4 + oo) * 64 + c];
#pragma unroll
            for (int ii = 0; ii < 5; ii++) {
                float4 x4 = *(const float4*)&sm[OXO + (ig * 5 + ii) * P + c];
#pragma unroll
                for (int oo = 0; oo < 4; oo++)
                    acc[ii][oo] += x4.x * w4[oo].x + x4.y * w4[oo].y
                                 + x4.z * w4[oo].z + x4.w * w4[oo].w;
            }
        }
#pragma unroll
        for (int oo = 0; oo < 4; oo++) {
            int o = og * 4 + oo;
            float b = __ldg(proj_b + h * HD + o);
#pragma unroll
            for (int ii = 0; ii < 5; ii++) {
                int i = ig * 5 + ii;
                xo_out[(((size_t)n * DIMC + h * HD + o) * TT + t) * VV + i] = acc[ii][oo] + b;
            }
        }
    }
}

extern "C" void kernel_launch(void* const* d_in, const int* in_sizes, int n_in,
                              void* d_out, int out_size)
{
    const float* x      = (const float*)d_in[0];
    const float* e      = (const float*)d_in[1];
    const float* kv_w   = (const float*)d_in[2];
    const float* q_w    = (const float*)d_in[3];
    const float* e_kv_w = (const float*)d_in[4];
    const float* e_q_w  = (const float*)d_in[5];
    const float* rpe    = (const float*)d_in[6];
    const float* outerp = (const float*)d_in[7];
    const float* alpha  = (const float*)d_in[8];
    const float* beta   = (const float*)d_in[9];
    const float* proj_w = (const float*)d_in[10];
    const float* proj_b = (const float*)d_in[11];
    const int*   hops   = (const int*)d_in[12];

    int nh = in_sizes[6] / DIMC;

    float* xo = (float*)d_out;
    float* eo = xo + (size_t)NB * DIMC * TT * VV;

    presplit_w<<<(1920 * 384 / 4 + 255) / 256, 256>>>(kv_w, q_w, e_kv_w, e_q_w);
    presplit_x<<<dim3(DIMC, NB, 2), 256>>>(x, e);

    cudaFuncSetAttribute(proj_mma, cudaFuncAttributeMaxDynamicSharedMemorySize, DYN_BYTES);
    proj_mma<<<dim3(13, 15, NB), 256, DYN_BYTES>>>();
    attn_kernel<<<dim3(HH, TT, NB), 128>>>(rpe, outerp, alpha, beta,
                                           proj_w, proj_b, hops, nh, xo, eo);
}

// round 12
// speedup vs baseline: 1.3966x; 1.3966x over previous
#include <cuda_runtime.h>
#include <cuda_bf16.h>
#include <math.h>
#include <stdint.h>

#define NB   64
#define TT   64
#define VV   25
#define DIMC 384
#define HH   6
#define HD   64
#define TV   1600                 // T*V
#define SL   39321600             // N*T*H*HD*V  (per-slot scratch size)
#define NSTRIDE 614400u           // T*H*HD*V    (per-n stride within a slot)
#define XPITCH 1664               // padded TV for cp.async (multiple of 128)

// Scratch: slots 0..4 = K, V, Q, EK, EQ, each [N,T,H,V,HD] fp32 (v-major inner)
__device__ float g_proj[5u * SL];
// Pre-split GEMM operands (bf16 hi/lo)
__device__ __nv_bfloat16 g_whi[1920 * 384];
__device__ __nv_bfloat16 g_wlo[1920 * 384];
__device__ __nv_bfloat16 g_xhi[2u * NB * DIMC * XPITCH];
__device__ __nv_bfloat16 g_xlo[2u * NB * DIMC * XPITCH];
// Pre-split, pre-swizzled per-head aux tiles (rpe 32x64, proj_w 64x64)
__device__ __align__(16) char g_rhi_sw[6 * 4096];
__device__ __align__(16) char g_rlo_sw[6 * 4096];
__device__ __align__(16) char g_pwhi_sw[6 * 8192];
__device__ __align__(16) char g_pwlo_sw[6 * 8192];

// ---------------- helpers ----------------
__device__ __forceinline__ uint32_t smem_u32(const void* p) {
    uint32_t a;
    asm("{ .reg .u64 t; cvta.to.shared.u64 t, %1; cvt.u32.u64 %0, t; }"
        : "=r"(a) : "l"(p));
    return a;
}
__device__ __forceinline__ void split4(float4 v, uint2& h, uint2& l) {
    __nv_bfloat162 h0 = __floats2bfloat162_rn(v.x, v.y);
    __nv_bfloat162 h1 = __floats2bfloat162_rn(v.z, v.w);
    float2 f0 = __bfloat1622float2(h0);
    float2 f1 = __bfloat1622float2(h1);
    __nv_bfloat162 l0 = __floats2bfloat162_rn(v.x - f0.x, v.y - f0.y);
    __nv_bfloat162 l1 = __floats2bfloat162_rn(v.z - f1.x, v.w - f1.y);
    h = make_uint2(*(uint32_t*)&h0, *(uint32_t*)&h1);
    l = make_uint2(*(uint32_t*)&l0, *(uint32_t*)&l1);
}
__device__ __forceinline__ void ldsm4(uint32_t addr, uint32_t* r) {
    asm volatile("ldmatrix.sync.aligned.m8n8.x4.shared.b16 {%0,%1,%2,%3}, [%4];"
                 : "=r"(r[0]), "=r"(r[1]), "=r"(r[2]), "=r"(r[3]) : "r"(addr));
}
__device__ __forceinline__ void ldsm4t(uint32_t addr, uint32_t* r) {
    asm volatile("ldmatrix.sync.aligned.m8n8.x4.trans.shared.b16 {%0,%1,%2,%3}, [%4];"
                 : "=r"(r[0]), "=r"(r[1]), "=r"(r[2]), "=r"(r[3]) : "r"(addr));
}
__device__ __forceinline__ void mma_bf16(float* c, const uint32_t* a, const uint32_t* b) {
    asm volatile("mma.sync.aligned.m16n8k16.row.col.f32.bf16.bf16.f32 "
                 "{%0,%1,%2,%3}, {%4,%5,%6,%7}, {%8,%9}, {%0,%1,%2,%3};"
                 : "+f"(c[0]), "+f"(c[1]), "+f"(c[2]), "+f"(c[3])
                 : "r"(a[0]), "r"(a[1]), "r"(a[2]), "r"(a[3]), "r"(b[0]), "r"(b[1]));
}
__device__ __forceinline__ void cp16(uint32_t dst, const void* src) {
    asm volatile("cp.async.cg.shared.global [%0], [%1], 16;" :: "r"(dst), "l"(src));
}
__device__ __forceinline__ void cp_commit() {
    asm volatile("cp.async.commit_group;" ::: "memory");
}
template <int N>
__device__ __forceinline__ void cp_wait() {
    asm volatile("cp.async.wait_group %0;" :: "n"(N) : "memory");
}
// swizzled byte offset within a 128B-row tile, bf16 col c
__device__ __forceinline__ uint32_t swz_off(int row, int c) {
    return (uint32_t)(row * 128 + (((c >> 3) ^ (row & 7)) * 16) + (c & 7) * 2);
}

// =====================================================================
// Pre-split kernels
// =====================================================================
__global__ __launch_bounds__(256) void presplit_w(
    const float* __restrict__ kv_w, const float* __restrict__ q_w,
    const float* __restrict__ e_kv_w, const float* __restrict__ e_q_w)
{
    int id = blockIdx.x * 256 + threadIdx.x;
    if (id >= 1920 * 384 / 4) return;
    int idx4 = id * 4;
    int r = idx4 / 384, c = idx4 % 384;
    const float* src;
    if      (r < 768)  src = kv_w   + (size_t)r * 384 + c;
    else if (r < 1152) src = q_w    + (size_t)(r - 768) * 384 + c;
    else if (r < 1536) src = e_kv_w + (size_t)(r - 1152) * 384 + c;
    else               src = e_q_w  + (size_t)(r - 1536) * 384 + c;
    float4 v = *(const float4*)src;
    uint2 h, l; split4(v, h, l);
    *(uint2*)&g_whi[idx4] = h;
    *(uint2*)&g_wlo[idx4] = l;
}

__global__ __launch_bounds__(256) void presplit_x(
    const float* __restrict__ x, const float* __restrict__ e)
{
    const int k = blockIdx.x, n = blockIdx.y, path = blockIdx.z;
    const float* src = (path ? e : x) + ((size_t)n * DIMC + k) * TV;
    size_t dst = ((size_t)(path * NB + n) * DIMC + k) * XPITCH;
    for (int l4 = threadIdx.x; l4 < XPITCH / 4; l4 += 256) {
        int f = l4 * 4;
        float4 v = (f < TV) ? *(const float4*)(src + f) : make_float4(0.f, 0.f, 0.f, 0.f);
        uint2 h, l; split4(v, h, l);
        *(uint2*)&g_xhi[dst + f] = h;
        *(uint2*)&g_xlo[dst + f] = l;
    }
}

// rpe (per-head 32x64, zero-padded) + proj_w (per-head 64x64) -> swizzled bf16 hi/lo
__global__ __launch_bounds__(256) void presplit_aux(
    const float* __restrict__ rpe, const float* __restrict__ proj_w, int nh)
{
    const int h = blockIdx.x;
    for (int idx = threadIdx.x; idx < 2048; idx += 256) {
        int row = idx >> 6, c = idx & 63;
        float val = (row < nh) ? rpe[(size_t)row * DIMC + h * 64 + c] : 0.f;
        __nv_bfloat16 hi = __float2bfloat16(val);
        __nv_bfloat16 lo = __float2bfloat16(val - __bfloat162float(hi));
        uint32_t off = swz_off(row, c);
        *(__nv_bfloat16*)(g_rhi_sw + h * 4096 + off) = hi;
        *(__nv_bfloat16*)(g_rlo_sw + h * 4096 + off) = lo;
    }
    for (int idx = threadIdx.x; idx < 4096; idx += 256) {
        int row = idx >> 6, c = idx & 63;
        float val = proj_w[((size_t)h * 64 + row) * 64 + c];
        __nv_bfloat16 hi = __float2bfloat16(val);
        __nv_bfloat16 lo = __float2bfloat16(val - __bfloat162float(hi));
        uint32_t off = swz_off(row, c);
        *(__nv_bfloat16*)(g_pwhi_sw + h * 8192 + off) = hi;
        *(__nv_bfloat16*)(g_pwlo_sw + h * 8192 + off) = lo;
    }
}

// =====================================================================
// Projection GEMM via mma.sync bf16 (unchanged).
// =====================================================================
#define A_PITCH 80
#define B_PITCH 272
#define A_BYTES (128 * A_PITCH)
#define B_BYTES (32 * B_PITCH)
#define STAGE_BYTES (2 * A_BYTES + 2 * B_BYTES)
#define DYN_BYTES (3 * STAGE_BYTES)

__global__ __launch_bounds__(256, 2)
void proj_mma()
{
    const int nt  = blockIdx.x;
    const int mt  = blockIdx.y;
    const int n   = blockIdx.z;
    const int tid = threadIdx.x;
    const int lane = tid & 31;
    const int w    = tid >> 5;
    const int wm   = w & 3;
    const int wn   = w >> 2;

    extern __shared__ char smem[];
    const uint32_t smem_b = smem_u32(smem);

    const int path = (mt >= 9);
    const int o_origin = (mt < 12) ? ((mt < 9) ? mt * 128 : (mt - 9) * 128)
                                   : (384 + (mt - 12) * 128);
    const int wrow0 = mt * 128;
    const int p0 = nt * 128;

    const __nv_bfloat16* Xhi = g_xhi + ((size_t)(path * NB + n) * DIMC) * XPITCH;
    const __nv_bfloat16* Xlo = g_xlo + ((size_t)(path * NB + n) * DIMC) * XPITCH;

    const int a_row0 = (tid * 2) >> 2;
    const int a_s0   = (tid * 2) & 3;
    const int b_row0 = (tid * 2) >> 4;
    const int b_s0   = (tid * 2) & 15;

    const uint32_t aoff = (uint32_t)((wm * 32 + (lane & 15)) * A_PITCH + (lane >> 4) * 16);
    const uint32_t boff = (uint32_t)((lane & 15) * B_PITCH + (wn * 64 + (lane >> 4) * 8) * 2);

    float acc[16][4];
#pragma unroll
    for (int i = 0; i < 16; i++)
#pragma unroll
        for (int j = 0; j < 4; j++) acc[i][j] = 0.f;

    auto issue = [&](int c) {
        const int k0 = c * 32;
        const uint32_t st = smem_b + (uint32_t)((c % 3) * STAGE_BYTES);
#pragma unroll
        for (int i = 0; i < 2; i++) {
            int ar = a_row0;
            int as = (a_s0 + i) & 3;
            if (a_s0 + i >= 4) { ar = a_row0 + 1; }
            size_t asrc = (size_t)(wrow0 + ar) * 384 + k0 + as * 8;
            uint32_t adst = st + (uint32_t)(ar * A_PITCH + as * 16);
            cp16(adst, g_whi + asrc);
            cp16(adst + A_BYTES, g_wlo + asrc);
            int br = b_row0 + ((b_s0 + i) >= 16 ? 1 : 0);
            int bs = (b_s0 + i) & 15;
            size_t bsrc = (size_t)(k0 + br) * XPITCH + p0 + bs * 8;
            uint32_t bdst = st + (uint32_t)(2 * A_BYTES + br * B_PITCH + bs * 16);
            cp16(bdst, Xhi + bsrc);
            cp16(bdst + B_BYTES, Xlo + bsrc);
        }
        cp_commit();
    };

    issue(0);
    issue(1);

    for (int c = 0; c < 12; ++c) {
        if (c < 11) cp_wait<1>(); else cp_wait<0>();
        __syncthreads();
        if (c < 10) issue(c + 2);

        const uint32_t stage = smem_b + (uint32_t)((c % 3) * STAGE_BYTES);
        const uint32_t aHi = stage + aoff;
        const uint32_t aLo = aHi + A_BYTES;
        const uint32_t bHi = stage + 2 * A_BYTES + boff;
        const uint32_t bLo = bHi + B_BYTES;
#pragma unroll
        for (int s = 0; s < 2; s++) {
            uint32_t Ah[2][4], Al[2][4];
#pragma unroll
            for (int m = 0; m < 2; m++) {
                ldsm4(aHi + m * 16 * A_PITCH + s * 32, Ah[m]);
                ldsm4(aLo + m * 16 * A_PITCH + s * 32, Al[m]);
            }
            uint32_t Bh[4][4], Bl[4][4];
#pragma unroll
            for (int g = 0; g < 4; g++) {
                ldsm4t(bHi + s * 16 * B_PITCH + g * 32, Bh[g]);
                ldsm4t(bLo + s * 16 * B_PITCH + g * 32, Bl[g]);
            }
#pragma unroll
            for (int m = 0; m < 2; m++)
#pragma unroll
                for (int g = 0; g < 4; g++)
#pragma unroll
                    for (int half = 0; half < 2; half++) {
                        float* cc = acc[m * 8 + g * 2 + half];
                        mma_bf16(cc, Ah[m], &Bh[g][half * 2]);
                        mma_bf16(cc, Ah[m], &Bl[g][half * 2]);
                        mma_bf16(cc, Al[m], &Bh[g][half * 2]);
                    }
        }
        __syncthreads();
    }

    const int g   = lane >> 2;
    const int tig = lane & 3;
#pragma unroll
    for (int m = 0; m < 2; m++) {
#pragma unroll
        for (int ntile = 0; ntile < 8; ntile++) {
#pragma unroll
            for (int j = 0; j < 4; j++) {
                int o_g = o_origin + wm * 32 + m * 16 + g + (j >> 1) * 8;
                uint32_t p = (uint32_t)(p0 + wn * 64 + ntile * 8 + tig * 2 + (j & 1));
                if (p < TV) {
                    int cdiv = o_g / 384;
                    int slot = cdiv + (path ? 3 : 0);
                    int rem  = o_g - cdiv * 384;
                    int hh = rem >> 6, dd = rem & 63;
                    uint32_t t = (p * 5243u) >> 17;
                    uint32_t v = p - t * 25u;
                    uint32_t addr = (uint32_t)slot * (uint32_t)SL + (uint32_t)n * NSTRIDE
                                  + t * 9600u + (uint32_t)hh * 1600u + v * 64u + (uint32_t)dd;
                    g_proj[addr] = acc[m * 8 + ntile][j];
                }
            }
        }
    }
}

// =====================================================================
// Kernel B: attention, fully tensor-core scores/qR/projection.
// One block (128 threads) per (n,t,h).
// Region A (char smA[40960]): phase 0-2 = 10 swizzled 32x128B bf16 tiles;
//   reused in phase 4-5: XOHI 0, XOLO 4096, PWHI 8192, PWLO 16384.
// sm floats: OS 0, OD 700, OQR 1400 (each 25x28).
// =====================================================================
#define QHI_B  0
#define QLO_B  4096
#define EQHI_B 8192
#define EQLO_B 12288
#define KEHI_B 16384
#define KELO_B 20480
#define EKHI_B 24576
#define EKLO_B 28672
#define RHI_B  32768
#define RLO_B  36864
#define XOHI_B 0
#define XOLO_B 4096
#define PWHI_B 8192
#define PWLO_B 16384
#define OS_F   0
#define OD_F   700
#define OQR_F  1400

__global__ __launch_bounds__(128) void attn_kernel(
    const float* __restrict__ outer,
    const float* __restrict__ alpha_p, const float* __restrict__ beta_p,
    const float* __restrict__ proj_b,
    const int* __restrict__ hops, int nh,
    float* __restrict__ xo_out, float* __restrict__ eo_out)
{
    const int h = blockIdx.x, t = blockIdx.y, n = blockIdx.z;
    const int tid = threadIdx.x;
    const int lane = tid & 31;
    const int w = tid >> 5;

    __shared__ __align__(16) char smA[40960];
    __shared__ float sm[2100];
    __shared__ unsigned char shops[640];
    const uint32_t smA_u = smem_u32(smA);

    const size_t base = (((size_t)n * TT + t) * HH + h) * (size_t)(HD * VV);

    // ---- phase 0: zero pads, load/split main tiles, load R tiles, hops ----
    for (int z = tid; z < 448; z += 128) {
        int r = z >> 3, c = z & 7;
        int mtx = r / 7, row = 25 + (r % 7);
        *(float4*)(smA + mtx * 4096 + row * 128 + c * 16) =
            make_float4(0.f, 0.f, 0.f, 0.f);
    }
    for (int l4 = tid; l4 < 400; l4 += 128) {
        int f = l4 * 4;
        int v = f >> 6, d = f & 63;
        float4 k4  = *(const float4*)&g_proj[0 * (size_t)SL + base + f];
        float4 q4  = *(const float4*)&g_proj[2 * (size_t)SL + base + f];
        float4 ek4 = *(const float4*)&g_proj[3 * (size_t)SL + base + f];
        float4 eq4 = *(const float4*)&g_proj[4 * (size_t)SL + base + f];
        float4 ke4 = make_float4(k4.x + ek4.x, k4.y + ek4.y, k4.z + ek4.z, k4.w + ek4.w);
        uint32_t off = swz_off(v, d);
        uint2 hh, ll;
        split4(q4, hh, ll);
        *(uint2*)(smA + QHI_B + off) = hh;  *(uint2*)(smA + QLO_B + off) = ll;
        split4(eq4, hh, ll);
        *(uint2*)(smA + EQHI_B + off) = hh; *(uint2*)(smA + EQLO_B + off) = ll;
        split4(ke4, hh, ll);
        *(uint2*)(smA + KEHI_B + off) = hh; *(uint2*)(smA + KELO_B + off) = ll;
        split4(ek4, hh, ll);
        *(uint2*)(smA + EKHI_B + off) = hh; *(uint2*)(smA + EKLO_B + off) = ll;
    }
    for (int i16 = tid; i16 < 256; i16 += 128) {
        *(uint4*)(smA + RHI_B + i16 * 16) = *(const uint4*)(g_rhi_sw + h * 4096 + i16 * 16);
        *(uint4*)(smA + RLO_B + i16 * 16) = *(const uint4*)(g_rlo_sw + h * 4096 + i16 * 16);
    }
    for (int l = tid; l < 625; l += 128) shops[l] = (unsigned char)hops[l];
    __syncthreads();

    // ---- phase 2: three GEMMs via mma (S1=Q.KE', G2=EQ.EK', QR=Q.R') ----
    {
        const int mt = w & 1;
        const int nb = (w >> 1) * 16;
        const int arow = mt * 16 + (lane & 15);
        const int brow = nb + (lane & 15);
        float accS[2][4], accD[2][4], accR[2][4];
#pragma unroll
        for (int i = 0; i < 2; i++)
#pragma unroll
            for (int j = 0; j < 4; j++) { accS[i][j] = 0.f; accD[i][j] = 0.f; accR[i][j] = 0.f; }

#pragma unroll
        for (int s = 0; s < 4; s++) {
            uint32_t abyte = (uint32_t)(arow * 128 + (((s * 2 + (lane >> 4)) ^ (arow & 7)) * 16));
            uint32_t bbyte = (uint32_t)(brow * 128 + (((s * 2 + (lane >> 4)) ^ (brow & 7)) * 16));
            uint32_t qh[4], ql[4], eqh[4], eql[4];
            uint32_t keh[4], kel[4], ekh[4], ekl[4], rh[4], rl[4];
            ldsm4(smA_u + QHI_B  + abyte, qh);
            ldsm4(smA_u + QLO_B  + abyte, ql);
            ldsm4(smA_u + EQHI_B + abyte, eqh);
            ldsm4(smA_u + EQLO_B + abyte, eql);
            ldsm4(smA_u + KEHI_B + bbyte, keh);
            ldsm4(smA_u + KELO_B + bbyte, kel);
            ldsm4(smA_u + EKHI_B + bbyte, ekh);
            ldsm4(smA_u + EKLO_B + bbyte, ekl);
            ldsm4(smA_u + RHI_B  + bbyte, rh);
            ldsm4(smA_u + RLO_B  + bbyte, rl);
#pragma unroll
            for (int ns = 0; ns < 2; ns++) {
                uint32_t bKEh[2] = {keh[ns], keh[ns + 2]};
                uint32_t bKEl[2] = {kel[ns], kel[ns + 2]};
                uint32_t bEKh[2] = {ekh[ns], ekh[ns + 2]};
                uint32_t bEKl[2] = {ekl[ns], ekl[ns + 2]};
                uint32_t bRh[2]  = {rh[ns],  rh[ns + 2]};
                uint32_t bRl[2]  = {rl[ns],  rl[ns + 2]};
                mma_bf16(accS[ns], qh, bKEh);
                mma_bf16(accS[ns], qh, bKEl);
                mma_bf16(accS[ns], ql, bKEh);
                mma_bf16(accD[ns], eqh, bEKh);
                mma_bf16(accD[ns], eqh, bEKl);
                mma_bf16(accD[ns], eql, bEKh);
                mma_bf16(accR[ns], qh, bRh);
                mma_bf16(accR[ns], qh, bRl);
                mma_bf16(accR[ns], ql, bRh);
            }
        }
        // store qR (cols < nh), sync, then S/D epilogue with hop bias
#pragma unroll
        for (int ns = 0; ns < 2; ns++) {
#pragma unroll
            for (int j = 0; j < 4; j++) {
                int row = mt * 16 + (lane >> 2) + (j >> 1) * 8;
                int col = nb + ns * 8 + (lane & 3) * 2 + (j & 1);
                if (row < 25 && col < nh)
                    sm[OQR_F + row * 28 + col] = accR[ns][j];
            }
        }
        __syncthreads();
#pragma unroll
        for (int ns = 0; ns < 2; ns++) {
#pragma unroll
            for (int j = 0; j < 4; j++) {
                int row = mt * 16 + (lane >> 2) + (j >> 1) * 8;
                int col = nb + ns * 8 + (lane & 3) * 2 + (j & 1);
                if (row < 25 && col < 25) {
                    float g2 = accD[ns][j];
                    float b = sm[OQR_F + row * 28 + shops[row * 25 + col]];
                    sm[OS_F + row * 28 + col] = accS[ns][j] + g2 + b;
                    sm[OD_F + row * 28 + col] = g2;
                }
            }
        }
    }
    __syncthreads();

    const float alpha = __ldg(alpha_p);
    const float beta  = __ldg(beta_p);
    const float scale = 0.125f;

    // ---- phase 3: softmax (50 rows), fold alpha/outer/beta ----
    if (tid < 50) {
        int i = tid % 25;
        float* row = &sm[(tid < 25 ? OS_F : OD_F) + i * 28];
        float m = -1e30f;
#pragma unroll
        for (int j = 0; j < 25; j++) m = fmaxf(m, row[j]);
        float ebuf[25];
        float s = 0.f;
#pragma unroll
        for (int j = 0; j < 25; j++) { float v = expf((row[j] - m) * scale); ebuf[j] = v; s += v; }
        float inv = 1.f / s;
        if (tid < 25) {
            const float* orow = outer + (size_t)h * 625 + i * 25;
#pragma unroll
            for (int j = 0; j < 25; j++)
                row[j] = alpha * (ebuf[j] * inv) + __ldg(orow + j);
        } else {
#pragma unroll
            for (int j = 0; j < 25; j++)
                row[j] = beta * (ebuf[j] * inv);
        }
    }
    __syncthreads();

    // ---- phase 4: AV (V from gmem); XO -> split bf16 smem; load PW tiles ----
    for (int z = tid; z < 112; z += 128) {
        int m = z / 56, r = 25 + ((z % 56) >> 3), c = z & 7;
        *(float4*)(smA + (m ? XOLO_B : XOHI_B) + r * 128 + c * 16) =
            make_float4(0.f, 0.f, 0.f, 0.f);
    }
    for (int i16 = tid; i16 < 512; i16 += 128) {
        *(uint4*)(smA + PWHI_B + i16 * 16) = *(const uint4*)(g_pwhi_sw + h * 8192 + i16 * 16);
        *(uint4*)(smA + PWLO_B + i16 * 16) = *(const uint4*)(g_pwlo_sw + h * 8192 + i16 * 16);
    }
    if (tid < 80) {
        int ig = tid / 16;
        int dg = tid % 16;
        float aX[5][4], aE[5][4];
#pragma unroll
        for (int ii = 0; ii < 5; ii++)
#pragma unroll
            for (int dd = 0; dd < 4; dd++) { aX[ii][dd] = 0.f; aE[ii][dd] = 0.f; }
#pragma unroll
        for (int j = 0; j < 25; j++) {
            float4 v4 = __ldg((const float4*)&g_proj[1 * (size_t)SL + base + j * 64 + dg * 4]);
#pragma unroll
            for (int ii = 0; ii < 5; ii++) {
                float a  = sm[OS_F + (ig * 5 + ii) * 28 + j];
                float dc = sm[OD_F + (ig * 5 + ii) * 28 + j];
                aX[ii][0] += a * v4.x;  aX[ii][1] += a * v4.y;
                aX[ii][2] += a * v4.z;  aX[ii][3] += a * v4.w;
                aE[ii][0] += dc * v4.x; aE[ii][1] += dc * v4.y;
                aE[ii][2] += dc * v4.z; aE[ii][3] += dc * v4.w;
            }
        }
        const int d0 = dg * 4;
#pragma unroll
        for (int ii = 0; ii < 5; ii++) {
            int i = ig * 5 + ii;
#pragma unroll
            for (int dd = 0; dd < 4; dd++)
                eo_out[(((size_t)n * DIMC + h * HD + d0 + dd) * TT + t) * VV + i] = aE[ii][dd];
            float4 xv = make_float4(aX[ii][0], aX[ii][1], aX[ii][2], aX[ii][3]);
            uint2 hh, ll; split4(xv, hh, ll);
            uint32_t off = swz_off(i, d0);
            *(uint2*)(smA + XOHI_B + off) = hh;
            *(uint2*)(smA + XOLO_B + off) = ll;
        }
    }
    __syncthreads();

    // ---- phase 5: grouped projection via mma: OUT(25x64) = XO(25x64).W'(64x64) ----
    {
        const int mt = w & 1;
        const int ng = w >> 1;           // ntiles ng*2, ng*2+1
        const int arow = mt * 16 + (lane & 15);
        float accP[2][2][4];
#pragma unroll
        for (int a = 0; a < 2; a++)
#pragma unroll
            for (int b = 0; b < 2; b++)
#pragma unroll
                for (int j = 0; j < 4; j++) accP[a][b][j] = 0.f;

#pragma unroll
        for (int s = 0; s < 4; s++) {
            uint32_t abyte = (uint32_t)(arow * 128 + (((s * 2 + (lane >> 4)) ^ (arow & 7)) * 16));
            uint32_t xh[4], xl[4];
            ldsm4(smA_u + XOHI_B + abyte, xh);
            ldsm4(smA_u + XOLO_B + abyte, xl);
#pragma unroll
            for (int nt2 = 0; nt2 < 2; nt2++) {
                int brow = (ng * 2 + nt2) * 16 + (lane & 15);
                uint32_t bbyte = (uint32_t)(brow * 128 + (((s * 2 + (lane >> 4)) ^ (brow & 7)) * 16));
                uint32_t wh[4], wl[4];
                ldsm4(smA_u + PWHI_B + bbyte, wh);
                ldsm4(smA_u + PWLO_B + bbyte, wl);
#pragma unroll
                for (int ns = 0; ns < 2; ns++) {
                    uint32_t bh[2] = {wh[ns], wh[ns + 2]};
                    uint32_t bl[2] = {wl[ns], wl[ns + 2]};
                    mma_bf16(accP[nt2][ns], xh, bh);
                    mma_bf16(accP[nt2][ns], xh, bl);
                    mma_bf16(accP[nt2][ns], xl, bh);
                }
            }
        }
#pragma unroll
        for (int nt2 = 0; nt2 < 2; nt2++) {
#pragma unroll
            for (int ns = 0; ns < 2; ns++) {
#pragma unroll
                for (int j = 0; j < 4; j++) {
                    int row = mt * 16 + (lane >> 2) + (j >> 1) * 8;
                    int col = (ng * 2 + nt2) * 16 + ns * 8 + (lane & 3) * 2 + (j & 1);
                    if (row < 25) {
                        float b = __ldg(proj_b + h * HD + col);
                        xo_out[(((size_t)n * DIMC + h * HD + col) * TT + t) * VV + row] =
                            accP[nt2][ns][j] + b;
                    }
                }
            }
        }
    }
}

extern "C" void kernel_launch(void* const* d_in, const int* in_sizes, int n_in,
                              void* d_out, int out_size)
{
    const float* x      = (const float*)d_in[0];
    const float* e      = (const float*)d_in[1];
    const float* kv_w   = (const float*)d_in[2];
    const float* q_w    = (const float*)d_in[3];
    const float* e_kv_w = (const float*)d_in[4];
    const float* e_q_w  = (const float*)d_in[5];
    const float* rpe    = (const float*)d_in[6];
    const float* outerp = (const float*)d_in[7];
    const float* alpha  = (const float*)d_in[8];
    const float* beta   = (const float*)d_in[9];
    const float* proj_w = (const float*)d_in[10];
    const float* proj_b = (const float*)d_in[11];
    const int*   hops   = (const int*)d_in[12];

    int nh = in_sizes[6] / DIMC;

    float* xo = (float*)d_out;
    float* eo = xo + (size_t)NB * DIMC * TT * VV;

    presplit_w<<<(1920 * 384 / 4 + 255) / 256, 256>>>(kv_w, q_w, e_kv_w, e_q_w);
    presplit_x<<<dim3(DIMC, NB, 2), 256>>>(x, e);
    presplit_aux<<<6, 256>>>(rpe, proj_w, nh);

    cudaFuncSetAttribute(proj_mma, cudaFuncAttributeMaxDynamicSharedMemorySize, DYN_BYTES);
    proj_mma<<<dim3(13, 15, NB), 256, DYN_BYTES>>>();
    attn_kernel<<<dim3(HH, TT, NB), 128>>>(outerp, alpha, beta,
                                           proj_b, hops, nh, xo, eo);
}

// round 13
// speedup vs baseline: 1.7347x; 1.2420x over previous
#include <cuda_runtime.h>
#include <cuda_fp16.h>
#include <math.h>
#include <stdint.h>

#define NB   64
#define TT   64
#define VV   25
#define DIMC 384
#define HH   6
#define HD   64
#define TV   1600                 // T*V
#define SL   39321600             // N*T*H*HD*V  (per-slot scratch size)
#define NSTRIDE 614400u           // T*H*HD*V    (per-n stride within a slot)
#define XPITCH 1664               // padded TV for cp.async (multiple of 128)

// Scratch: slots 0..4 = K, V, Q, EK, EQ, each [N,T,H,V,HD] fp32 (v-major inner)
__device__ float g_proj[5u * SL];
// Pre-split GEMM operands: W fp16 hi/lo, X single fp16
__device__ __half g_whi[1920 * 384];
__device__ __half g_wlo[1920 * 384];
__device__ __half g_x16[2u * NB * DIMC * XPITCH];
// Pre-split, pre-swizzled per-head aux tiles (rpe 32x64, proj_w 64x64), fp16 hi/lo
__device__ __align__(16) char g_rhi_sw[6 * 4096];
__device__ __align__(16) char g_rlo_sw[6 * 4096];
__device__ __align__(16) char g_pwhi_sw[6 * 8192];
__device__ __align__(16) char g_pwlo_sw[6 * 8192];

// ---------------- helpers ----------------
__device__ __forceinline__ uint32_t smem_u32(const void* p) {
    uint32_t a;
    asm("{ .reg .u64 t; cvta.to.shared.u64 t, %1; cvt.u32.u64 %0, t; }"
        : "=r"(a) : "l"(p));
    return a;
}
__device__ __forceinline__ void split4h(float4 v, uint2& h, uint2& l) {
    __half2 h0 = __floats2half2_rn(v.x, v.y);
    __half2 h1 = __floats2half2_rn(v.z, v.w);
    float2 f0 = __half22float2(h0);
    float2 f1 = __half22float2(h1);
    __half2 l0 = __floats2half2_rn(v.x - f0.x, v.y - f0.y);
    __half2 l1 = __floats2half2_rn(v.z - f1.x, v.w - f1.y);
    h = make_uint2(*(uint32_t*)&h0, *(uint32_t*)&h1);
    l = make_uint2(*(uint32_t*)&l0, *(uint32_t*)&l1);
}
__device__ __forceinline__ uint2 cvt4h(float4 v) {
    __half2 h0 = __floats2half2_rn(v.x, v.y);
    __half2 h1 = __floats2half2_rn(v.z, v.w);
    return make_uint2(*(uint32_t*)&h0, *(uint32_t*)&h1);
}
__device__ __forceinline__ void ldsm4(uint32_t addr, uint32_t* r) {
    asm volatile("ldmatrix.sync.aligned.m8n8.x4.shared.b16 {%0,%1,%2,%3}, [%4];"
                 : "=r"(r[0]), "=r"(r[1]), "=r"(r[2]), "=r"(r[3]) : "r"(addr));
}
__device__ __forceinline__ void ldsm4t(uint32_t addr, uint32_t* r) {
    asm volatile("ldmatrix.sync.aligned.m8n8.x4.trans.shared.b16 {%0,%1,%2,%3}, [%4];"
                 : "=r"(r[0]), "=r"(r[1]), "=r"(r[2]), "=r"(r[3]) : "r"(addr));
}
__device__ __forceinline__ void mma_f16(float* c, const uint32_t* a, const uint32_t* b) {
    asm volatile("mma.sync.aligned.m16n8k16.row.col.f32.f16.f16.f32 "
                 "{%0,%1,%2,%3}, {%4,%5,%6,%7}, {%8,%9}, {%0,%1,%2,%3};"
                 : "+f"(c[0]), "+f"(c[1]), "+f"(c[2]), "+f"(c[3])
                 : "r"(a[0]), "r"(a[1]), "r"(a[2]), "r"(a[3]), "r"(b[0]), "r"(b[1]));
}
__device__ __forceinline__ void cp16(uint32_t dst, const void* src) {
    asm volatile("cp.async.cg.shared.global [%0], [%1], 16;" :: "r"(dst), "l"(src));
}
__device__ __forceinline__ void cp_commit() {
    asm volatile("cp.async.commit_group;" ::: "memory");
}
template <int N>
__device__ __forceinline__ void cp_wait() {
    asm volatile("cp.async.wait_group %0;" :: "n"(N) : "memory");
}
// swizzled byte offset within a 128B-row tile, fp16 col c
__device__ __forceinline__ uint32_t swz_off(int row, int c) {
    return (uint32_t)(row * 128 + (((c >> 3) ^ (row & 7)) * 16) + (c & 7) * 2);
}

// =====================================================================
// Pre-split kernels
// =====================================================================
__global__ __launch_bounds__(256) void presplit_w(
    const float* __restrict__ kv_w, const float* __restrict__ q_w,
    const float* __restrict__ e_kv_w, const float* __restrict__ e_q_w)
{
    int id = blockIdx.x * 256 + threadIdx.x;
    if (id >= 1920 * 384 / 4) return;
    int idx4 = id * 4;
    int r = idx4 / 384, c = idx4 % 384;
    const float* src;
    if      (r < 768)  src = kv_w   + (size_t)r * 384 + c;
    else if (r < 1152) src = q_w    + (size_t)(r - 768) * 384 + c;
    else if (r < 1536) src = e_kv_w + (size_t)(r - 1152) * 384 + c;
    else               src = e_q_w  + (size_t)(r - 1536) * 384 + c;
    float4 v = *(const float4*)src;
    uint2 h, l; split4h(v, h, l);
    *(uint2*)&g_whi[idx4] = h;
    *(uint2*)&g_wlo[idx4] = l;
}

__global__ __launch_bounds__(256) void presplit_x(
    const float* __restrict__ x, const float* __restrict__ e)
{
    const int k = blockIdx.x, n = blockIdx.y, path = blockIdx.z;
    const float* src = (path ? e : x) + ((size_t)n * DIMC + k) * TV;
    size_t dst = ((size_t)(path * NB + n) * DIMC + k) * XPITCH;
    for (int l4 = threadIdx.x; l4 < XPITCH / 4; l4 += 256) {
        int f = l4 * 4;
        float4 v = (f < TV) ? *(const float4*)(src + f) : make_float4(0.f, 0.f, 0.f, 0.f);
        *(uint2*)&g_x16[dst + f] = cvt4h(v);
    }
}

// rpe (per-head 32x64, zero-padded) + proj_w (per-head 64x64) -> swizzled fp16 hi/lo
__global__ __launch_bounds__(256) void presplit_aux(
    const float* __restrict__ rpe, const float* __restrict__ proj_w, int nh)
{
    const int h = blockIdx.x;
    for (int idx = threadIdx.x; idx < 2048; idx += 256) {
        int row = idx >> 6, c = idx & 63;
        float val = (row < nh) ? rpe[(size_t)row * DIMC + h * 64 + c] : 0.f;
        __half hi = __float2half(val);
        __half lo = __float2half(val - __half2float(hi));
        uint32_t off = swz_off(row, c);
        *(__half*)(g_rhi_sw + h * 4096 + off) = hi;
        *(__half*)(g_rlo_sw + h * 4096 + off) = lo;
    }
    for (int idx = threadIdx.x; idx < 4096; idx += 256) {
        int row = idx >> 6, c = idx & 63;
        float val = proj_w[((size_t)h * 64 + row) * 64 + c];
        __half hi = __float2half(val);
        __half lo = __float2half(val - __half2float(hi));
        uint32_t off = swz_off(row, c);
        *(__half*)(g_pwhi_sw + h * 8192 + off) = hi;
        *(__half*)(g_pwlo_sw + h * 8192 + off) = lo;
    }
}

// =====================================================================
// Projection GEMM via mma.sync fp16 (W split hi/lo, X single; 2 MMAs/tile).
// CTA tile: M=128 x N=128, K=384, BK=32, 3-stage cp.async pipeline.
// =====================================================================
#define A_PITCH 80
#define B_PITCH 272
#define A_BYTES (128 * A_PITCH)
#define B_BYTES (32 * B_PITCH)
#define STAGE_BYTES (2 * A_BYTES + B_BYTES)      // 29184
#define DYN_BYTES (3 * STAGE_BYTES)              // 87552

__global__ __launch_bounds__(256, 2)
void proj_mma()
{
    const int nt  = blockIdx.x;
    const int mt  = blockIdx.y;
    const int n   = blockIdx.z;
    const int tid = threadIdx.x;
    const int lane = tid & 31;
    const int w    = tid >> 5;
    const int wm   = w & 3;
    const int wn   = w >> 2;

    extern __shared__ char smem[];
    const uint32_t smem_b = smem_u32(smem);

    const int path = (mt >= 9);
    const int o_origin = (mt < 12) ? ((mt < 9) ? mt * 128 : (mt - 9) * 128)
                                   : (384 + (mt - 12) * 128);
    const int wrow0 = mt * 128;
    const int p0 = nt * 128;

    const __half* X16 = g_x16 + ((size_t)(path * NB + n) * DIMC) * XPITCH;

    const int a_row0 = (tid * 2) >> 2;
    const int a_s0   = (tid * 2) & 3;
    const int b_row0 = (tid * 2) >> 4;
    const int b_s0   = (tid * 2) & 15;

    const uint32_t aoff = (uint32_t)((wm * 32 + (lane & 15)) * A_PITCH + (lane >> 4) * 16);
    const uint32_t boff = (uint32_t)((lane & 15) * B_PITCH + (wn * 64 + (lane >> 4) * 8) * 2);

    float acc[16][4];
#pragma unroll
    for (int i = 0; i < 16; i++)
#pragma unroll
        for (int j = 0; j < 4; j++) acc[i][j] = 0.f;

    auto issue = [&](int c) {
        const int k0 = c * 32;
        const uint32_t st = smem_b + (uint32_t)((c % 3) * STAGE_BYTES);
#pragma unroll
        for (int i = 0; i < 2; i++) {
            int ar = a_row0;
            int as = (a_s0 + i) & 3;
            if (a_s0 + i >= 4) { ar = a_row0 + 1; }
            size_t asrc = (size_t)(wrow0 + ar) * 384 + k0 + as * 8;
            uint32_t adst = st + (uint32_t)(ar * A_PITCH + as * 16);
            cp16(adst, g_whi + asrc);
            cp16(adst + A_BYTES, g_wlo + asrc);
            int br = b_row0 + ((b_s0 + i) >= 16 ? 1 : 0);
            int bs = (b_s0 + i) & 15;
            size_t bsrc = (size_t)(k0 + br) * XPITCH + p0 + bs * 8;
            uint32_t bdst = st + (uint32_t)(2 * A_BYTES + br * B_PITCH + bs * 16);
            cp16(bdst, X16 + bsrc);
        }
        cp_commit();
    };

    issue(0);
    issue(1);

    for (int c = 0; c < 12; ++c) {
        if (c < 11) cp_wait<1>(); else cp_wait<0>();
        __syncthreads();
        if (c < 10) issue(c + 2);

        const uint32_t stage = smem_b + (uint32_t)((c % 3) * STAGE_BYTES);
        const uint32_t aHi = stage + aoff;
        const uint32_t aLo = aHi + A_BYTES;
        const uint32_t bB  = stage + 2 * A_BYTES + boff;
#pragma unroll
        for (int s = 0; s < 2; s++) {
            uint32_t Ah[2][4], Al[2][4];
#pragma unroll
            for (int m = 0; m < 2; m++) {
                ldsm4(aHi + m * 16 * A_PITCH + s * 32, Ah[m]);
                ldsm4(aLo + m * 16 * A_PITCH + s * 32, Al[m]);
            }
            uint32_t Bh[4][4];
#pragma unroll
            for (int g = 0; g < 4; g++)
                ldsm4t(bB + s * 16 * B_PITCH + g * 32, Bh[g]);
#pragma unroll
            for (int m = 0; m < 2; m++)
#pragma unroll
                for (int g = 0; g < 4; g++)
#pragma unroll
                    for (int half = 0; half < 2; half++) {
                        float* cc = acc[m * 8 + g * 2 + half];
                        mma_f16(cc, Ah[m], &Bh[g][half * 2]);
                        mma_f16(cc, Al[m], &Bh[g][half * 2]);
                    }
        }
        __syncthreads();
    }

    const int g   = lane >> 2;
    const int tig = lane & 3;
#pragma unroll
    for (int m = 0; m < 2; m++) {
#pragma unroll
        for (int ntile = 0; ntile < 8; ntile++) {
#pragma unroll
            for (int j = 0; j < 4; j++) {
                int o_g = o_origin + wm * 32 + m * 16 + g + (j >> 1) * 8;
                uint32_t p = (uint32_t)(p0 + wn * 64 + ntile * 8 + tig * 2 + (j & 1));
                if (p < TV) {
                    int cdiv = o_g / 384;
                    int slot = cdiv + (path ? 3 : 0);
                    int rem  = o_g - cdiv * 384;
                    int hh = rem >> 6, dd = rem & 63;
                    uint32_t t = (p * 5243u) >> 17;
                    uint32_t v = p - t * 25u;
                    uint32_t addr = (uint32_t)slot * (uint32_t)SL + (uint32_t)n * NSTRIDE
                                  + t * 9600u + (uint32_t)hh * 1600u + v * 64u + (uint32_t)dd;
                    g_proj[addr] = acc[m * 8 + ntile][j];
                }
            }
        }
    }
}

// =====================================================================
// Kernel B: attention, tensor-core scores/qR/projection, fp16 2-MMA.
// One block (128 threads) per (n,t,h).
// Region A (char smA[32768]): 8 swizzled 32x128B fp16 tiles;
//   phase 4-5 reuse: XO16 0, PWHI 4096, PWLO 12288.
// sm floats: OS 0, OD 700, OQR 1400.
// =====================================================================
#define Q16_B  0
#define EQ16_B 4096
#define KEHI_B 8192
#define KELO_B 12288
#define EKHI_B 16384
#define EKLO_B 20480
#define RHI_B  24576
#define RLO_B  28672
#define XO16_B 0
#define PWHI_B 4096
#define PWLO_B 12288
#define OS_F   0
#define OD_F   700
#define OQR_F  1400

__global__ __launch_bounds__(128) void attn_kernel(
    const float* __restrict__ outer,
    const float* __restrict__ alpha_p, const float* __restrict__ beta_p,
    const float* __restrict__ proj_b,
    const int* __restrict__ hops, int nh,
    float* __restrict__ xo_out, float* __restrict__ eo_out)
{
    const int h = blockIdx.x, t = blockIdx.y, n = blockIdx.z;
    const int tid = threadIdx.x;
    const int lane = tid & 31;
    const int w = tid >> 5;

    __shared__ __align__(16) char smA[32768];
    __shared__ float sm[2100];
    __shared__ unsigned char shops[640];
    const uint32_t smA_u = smem_u32(smA);

    const size_t base = (((size_t)n * TT + t) * HH + h) * (size_t)(HD * VV);

    // ---- phase 0: zero pad rows of all 8 tiles + load/split + R + hops ----
    for (int z = tid; z < 448; z += 128) {
        int r = z >> 3, c = z & 7;
        int mtx = r / 7, row = 25 + (r % 7);
        *(float4*)(smA + mtx * 4096 + row * 128 + c * 16) =
            make_float4(0.f, 0.f, 0.f, 0.f);
    }
    for (int l4 = tid; l4 < 400; l4 += 128) {
        int f = l4 * 4;
        int v = f >> 6, d = f & 63;
        float4 k4  = *(const float4*)&g_proj[0 * (size_t)SL + base + f];
        float4 q4  = *(const float4*)&g_proj[2 * (size_t)SL + base + f];
        float4 ek4 = *(const float4*)&g_proj[3 * (size_t)SL + base + f];
        float4 eq4 = *(const float4*)&g_proj[4 * (size_t)SL + base + f];
        float4 ke4 = make_float4(k4.x + ek4.x, k4.y + ek4.y, k4.z + ek4.z, k4.w + ek4.w);
        uint32_t off = swz_off(v, d);
        *(uint2*)(smA + Q16_B  + off) = cvt4h(q4);
        *(uint2*)(smA + EQ16_B + off) = cvt4h(eq4);
        uint2 hh, ll;
        split4h(ke4, hh, ll);
        *(uint2*)(smA + KEHI_B + off) = hh; *(uint2*)(smA + KELO_B + off) = ll;
        split4h(ek4, hh, ll);
        *(uint2*)(smA + EKHI_B + off) = hh; *(uint2*)(smA + EKLO_B + off) = ll;
    }
    for (int i16 = tid; i16 < 256; i16 += 128) {
        *(uint4*)(smA + RHI_B + i16 * 16) = *(const uint4*)(g_rhi_sw + h * 4096 + i16 * 16);
        *(uint4*)(smA + RLO_B + i16 * 16) = *(const uint4*)(g_rlo_sw + h * 4096 + i16 * 16);
    }
    for (int l = tid; l < 625; l += 128) shops[l] = (unsigned char)hops[l];
    __syncthreads();

    // ---- phase 2: three GEMMs via mma (S1=Q.KE', G2=EQ.EK', QR=Q.R') ----
    {
        const int mt = w & 1;
        const int nb = (w >> 1) * 16;
        const int arow = mt * 16 + (lane & 15);
        const int brow = nb + (lane & 15);
        float accS[2][4], accD[2][4], accR[2][4];
#pragma unroll
        for (int i = 0; i < 2; i++)
#pragma unroll
            for (int j = 0; j < 4; j++) { accS[i][j] = 0.f; accD[i][j] = 0.f; accR[i][j] = 0.f; }

#pragma unroll
        for (int s = 0; s < 4; s++) {
            uint32_t abyte = (uint32_t)(arow * 128 + (((s * 2 + (lane >> 4)) ^ (arow & 7)) * 16));
            uint32_t bbyte = (uint32_t)(brow * 128 + (((s * 2 + (lane >> 4)) ^ (brow & 7)) * 16));
            uint32_t q[4], eq[4], keh[4], kel[4], ekh[4], ekl[4], rh[4], rl[4];
            ldsm4(smA_u + Q16_B  + abyte, q);
            ldsm4(smA_u + EQ16_B + abyte, eq);
            ldsm4(smA_u + KEHI_B + bbyte, keh);
            ldsm4(smA_u + KELO_B + bbyte, kel);
            ldsm4(smA_u + EKHI_B + bbyte, ekh);
            ldsm4(smA_u + EKLO_B + bbyte, ekl);
            ldsm4(smA_u + RHI_B  + bbyte, rh);
            ldsm4(smA_u + RLO_B  + bbyte, rl);
#pragma unroll
            for (int ns = 0; ns < 2; ns++) {
                uint32_t bKEh[2] = {keh[ns], keh[ns + 2]};
                uint32_t bKEl[2] = {kel[ns], kel[ns + 2]};
                uint32_t bEKh[2] = {ekh[ns], ekh[ns + 2]};
                uint32_t bEKl[2] = {ekl[ns], ekl[ns + 2]};
                uint32_t bRh[2]  = {rh[ns],  rh[ns + 2]};
                uint32_t bRl[2]  = {rl[ns],  rl[ns + 2]};
                mma_f16(accS[ns], q, bKEh);
                mma_f16(accS[ns], q, bKEl);
                mma_f16(accD[ns], eq, bEKh);
                mma_f16(accD[ns], eq, bEKl);
                mma_f16(accR[ns], q, bRh);
                mma_f16(accR[ns], q, bRl);
            }
        }
        // store qR (cols < nh), sync, then S/D epilogue with hop bias
#pragma unroll
        for (int ns = 0; ns < 2; ns++) {
#pragma unroll
            for (int j = 0; j < 4; j++) {
                int row = mt * 16 + (lane >> 2) + (j >> 1) * 8;
                int col = nb + ns * 8 + (lane & 3) * 2 + (j & 1);
                if (row < 25 && col < nh)
                    sm[OQR_F + row * 28 + col] = accR[ns][j];
            }
        }
        __syncthreads();
#pragma unroll
        for (int ns = 0; ns < 2; ns++) {
#pragma unroll
            for (int j = 0; j < 4; j++) {
                int row = mt * 16 + (lane >> 2) + (j >> 1) * 8;
                int col = nb + ns * 8 + (lane & 3) * 2 + (j & 1);
                if (row < 25 && col < 25) {
                    float g2 = accD[ns][j];
                    float b = sm[OQR_F + row * 28 + shops[row * 25 + col]];
                    sm[OS_F + row * 28 + col] = accS[ns][j] + g2 + b;
                    sm[OD_F + row * 28 + col] = g2;
                }
            }
        }
    }
    __syncthreads();

    const float alpha = __ldg(alpha_p);
    const float beta  = __ldg(beta_p);
    const float scale = 0.125f;

    // ---- phase 3: softmax (50 rows), fold alpha/outer/beta ----
    if (tid < 50) {
        int i = tid % 25;
        float* row = &sm[(tid < 25 ? OS_F : OD_F) + i * 28];
        float m = -1e30f;
#pragma unroll
        for (int j = 0; j < 25; j++) m = fmaxf(m, row[j]);
        float ebuf[25];
        float s = 0.f;
#pragma unroll
        for (int j = 0; j < 25; j++) { float v = expf((row[j] - m) * scale); ebuf[j] = v; s += v; }
        float inv = 1.f / s;
        if (tid < 25) {
            const float* orow = outer + (size_t)h * 625 + i * 25;
#pragma unroll
            for (int j = 0; j < 25; j++)
                row[j] = alpha * (ebuf[j] * inv) + __ldg(orow + j);
        } else {
#pragma unroll
            for (int j = 0; j < 25; j++)
                row[j] = beta * (ebuf[j] * inv);
        }
    }
    __syncthreads();

    // ---- phase 4: AV (V from gmem); XO -> fp16 smem; load PW tiles ----
    for (int z = tid; z < 56; z += 128) {
        int r = 25 + (z >> 3), c = z & 7;
        *(float4*)(smA + XO16_B + r * 128 + c * 16) = make_float4(0.f, 0.f, 0.f, 0.f);
    }
    for (int i16 = tid; i16 < 512; i16 += 128) {
        *(uint4*)(smA + PWHI_B + i16 * 16) = *(const uint4*)(g_pwhi_sw + h * 8192 + i16 * 16);
        *(uint4*)(smA + PWLO_B + i16 * 16) = *(const uint4*)(g_pwlo_sw + h * 8192 + i16 * 16);
    }
    if (tid < 80) {
        int ig = tid / 16;
        int dg = tid % 16;
        float aX[5][4], aE[5][4];
#pragma unroll
        for (int ii = 0; ii < 5; ii++)
#pragma unroll
            for (int dd = 0; dd < 4; dd++) { aX[ii][dd] = 0.f; aE[ii][dd] = 0.f; }
#pragma unroll
        for (int j = 0; j < 25; j++) {
            float4 v4 = __ldg((const float4*)&g_proj[1 * (size_t)SL + base + j * 64 + dg * 4]);
#pragma unroll
            for (int ii = 0; ii < 5; ii++) {
                float a  = sm[OS_F + (ig * 5 + ii) * 28 + j];
                float dc = sm[OD_F + (ig * 5 + ii) * 28 + j];
                aX[ii][0] += a * v4.x;  aX[ii][1] += a * v4.y;
                aX[ii][2] += a * v4.z;  aX[ii][3] += a * v4.w;
                aE[ii][0] += dc * v4.x; aE[ii][1] += dc * v4.y;
                aE[ii][2] += dc * v4.z; aE[ii][3] += dc * v4.w;
            }
        }
        const int d0 = dg * 4;
#pragma unroll
        for (int ii = 0; ii < 5; ii++) {
            int i = ig * 5 + ii;
#pragma unroll
            for (int dd = 0; dd < 4; dd++)
                eo_out[(((size_t)n * DIMC + h * HD + d0 + dd) * TT + t) * VV + i] = aE[ii][dd];
            float4 xv = make_float4(aX[ii][0], aX[ii][1], aX[ii][2], aX[ii][3]);
            *(uint2*)(smA + XO16_B + swz_off(i, d0)) = cvt4h(xv);
        }
    }
    __syncthreads();

    // ---- phase 5: grouped projection via mma: OUT(25x64) = XO(25x64).W'(64x64) ----
    {
        const int mt = w & 1;
        const int ng = w >> 1;
        const int arow = mt * 16 + (lane & 15);
        float accP[2][2][4];
#pragma unroll
        for (int a = 0; a < 2; a++)
#pragma unroll
            for (int b = 0; b < 2; b++)
#pragma unroll
                for (int j = 0; j < 4; j++) accP[a][b][j] = 0.f;

#pragma unroll
        for (int s = 0; s < 4; s++) {
            uint32_t abyte = (uint32_t)(arow * 128 + (((s * 2 + (lane >> 4)) ^ (arow & 7)) * 16));
            uint32_t xh[4];
            ldsm4(smA_u + XO16_B + abyte, xh);
#pragma unroll
            for (int nt2 = 0; nt2 < 2; nt2++) {
                int brow = (ng * 2 + nt2) * 16 + (lane & 15);
                uint32_t bbyte = (uint32_t)(brow * 128 + (((s * 2 + (lane >> 4)) ^ (brow & 7)) * 16));
                uint32_t wh[4], wl[4];
                ldsm4(smA_u + PWHI_B + bbyte, wh);
                ldsm4(smA_u + PWLO_B + bbyte, wl);
#pragma unroll
                for (int ns = 0; ns < 2; ns++) {
                    uint32_t bh[2] = {wh[ns], wh[ns + 2]};
                    uint32_t bl[2] = {wl[ns], wl[ns + 2]};
                    mma_f16(accP[nt2][ns], xh, bh);
                    mma_f16(accP[nt2][ns], xh, bl);
                }
            }
        }
#pragma unroll
        for (int nt2 = 0; nt2 < 2; nt2++) {
#pragma unroll
            for (int ns = 0; ns < 2; ns++) {
#pragma unroll
                for (int j = 0; j < 4; j++) {
                    int row = mt * 16 + (lane >> 2) + (j >> 1) * 8;
                    int col = (ng * 2 + nt2) * 16 + ns * 8 + (lane & 3) * 2 + (j & 1);
                    if (row < 25) {
                        float b = __ldg(proj_b + h * HD + col);
                        xo_out[(((size_t)n * DIMC + h * HD + col) * TT + t) * VV + row] =
                            accP[nt2][ns][j] + b;
                    }
                }
            }
        }
    }
}

extern "C" void kernel_launch(void* const* d_in, const int* in_sizes, int n_in,
                              void* d_out, int out_size)
{
    const float* x      = (const float*)d_in[0];
    const float* e      = (const float*)d_in[1];
    const float* kv_w   = (const float*)d_in[2];
    const float* q_w    = (const float*)d_in[3];
    const float* e_kv_w = (const float*)d_in[4];
    const float* e_q_w  = (const float*)d_in[5];
    const float* rpe    = (const float*)d_in[6];
    const float* outerp = (const float*)d_in[7];
    const float* alpha  = (const float*)d_in[8];
    const float* beta   = (const float*)d_in[9];
    const float* proj_w = (const float*)d_in[10];
    const float* proj_b = (const float*)d_in[11];
    const int*   hops   = (const int*)d_in[12];

    int nh = in_sizes[6] / DIMC;

    float* xo = (float*)d_out;
    float* eo = xo + (size_t)NB * DIMC * TT * VV;

    presplit_w<<<(1920 * 384 / 4 + 255) / 256, 256>>>(kv_w, q_w, e_kv_w, e_q_w);
    presplit_x<<<dim3(DIMC, NB, 2), 256>>>(x, e);
    presplit_aux<<<6, 256>>>(rpe, proj_w, nh);

    cudaFuncSetAttribute(proj_mma, cudaFuncAttributeMaxDynamicSharedMemorySize, DYN_BYTES);
    proj_mma<<<dim3(13, 15, NB), 256, DYN_BYTES>>>();
    attn_kernel<<<dim3(HH, TT, NB), 128>>>(outerp, alpha, beta,
                                           proj_b, hops, nh, xo, eo);
}

// round 14
// speedup vs baseline: 1.8394x; 1.0604x over previous
#include <cuda_runtime.h>
#include <cuda_fp16.h>
#include <math.h>
#include <stdint.h>

#define NB   64
#define TT   64
#define VV   25
#define DIMC 384
#define HH   6
#define HD   64
#define TV   1600                 // T*V
#define SL   39321600             // N*T*H*HD*V  (per-slot scratch size)
#define NSTRIDE 614400u           // T*H*HD*V    (per-n stride within a slot)
#define XPITCH 1664               // padded TV for cp.async (multiple of 128)

// Scratch: slots 0..4 = K, V, Q, EK, EQ, each [N,T,H,V,HD] fp32 (v-major inner)
__device__ float g_proj[5u * SL];
// Pre-split GEMM operands: W fp16 hi/lo, X single fp16
__device__ __half g_whi[1920 * 384];
__device__ __half g_wlo[1920 * 384];
__device__ __half g_x16[2u * NB * DIMC * XPITCH];
// Pre-split, pre-swizzled per-head aux tiles (rpe 32x64, proj_w 64x64), fp16 hi/lo
__device__ __align__(16) char g_rhi_sw[6 * 4096];
__device__ __align__(16) char g_rlo_sw[6 * 4096];
__device__ __align__(16) char g_pwhi_sw[6 * 8192];
__device__ __align__(16) char g_pwlo_sw[6 * 8192];

// ---------------- helpers ----------------
__device__ __forceinline__ uint32_t smem_u32(const void* p) {
    uint32_t a;
    asm("{ .reg .u64 t; cvta.to.shared.u64 t, %1; cvt.u32.u64 %0, t; }"
        : "=r"(a) : "l"(p));
    return a;
}
__device__ __forceinline__ void split4h(float4 v, uint2& h, uint2& l) {
    __half2 h0 = __floats2half2_rn(v.x, v.y);
    __half2 h1 = __floats2half2_rn(v.z, v.w);
    float2 f0 = __half22float2(h0);
    float2 f1 = __half22float2(h1);
    __half2 l0 = __floats2half2_rn(v.x - f0.x, v.y - f0.y);
    __half2 l1 = __floats2half2_rn(v.z - f1.x, v.w - f1.y);
    h = make_uint2(*(uint32_t*)&h0, *(uint32_t*)&h1);
    l = make_uint2(*(uint32_t*)&l0, *(uint32_t*)&l1);
}
__device__ __forceinline__ uint2 cvt4h(float4 v) {
    __half2 h0 = __floats2half2_rn(v.x, v.y);
    __half2 h1 = __floats2half2_rn(v.z, v.w);
    return make_uint2(*(uint32_t*)&h0, *(uint32_t*)&h1);
}
__device__ __forceinline__ void ldsm4(uint32_t addr, uint32_t* r) {
    asm volatile("ldmatrix.sync.aligned.m8n8.x4.shared.b16 {%0,%1,%2,%3}, [%4];"
                 : "=r"(r[0]), "=r"(r[1]), "=r"(r[2]), "=r"(r[3]) : "r"(addr));
}
__device__ __forceinline__ void ldsm4t(uint32_t addr, uint32_t* r) {
    asm volatile("ldmatrix.sync.aligned.m8n8.x4.trans.shared.b16 {%0,%1,%2,%3}, [%4];"
                 : "=r"(r[0]), "=r"(r[1]), "=r"(r[2]), "=r"(r[3]) : "r"(addr));
}
__device__ __forceinline__ void mma_f16(float* c, const uint32_t* a, const uint32_t* b) {
    asm volatile("mma.sync.aligned.m16n8k16.row.col.f32.f16.f16.f32 "
                 "{%0,%1,%2,%3}, {%4,%5,%6,%7}, {%8,%9}, {%0,%1,%2,%3};"
                 : "+f"(c[0]), "+f"(c[1]), "+f"(c[2]), "+f"(c[3])
                 : "r"(a[0]), "r"(a[1]), "r"(a[2]), "r"(a[3]), "r"(b[0]), "r"(b[1]));
}
__device__ __forceinline__ void cp16(uint32_t dst, const void* src) {
    asm volatile("cp.async.cg.shared.global [%0], [%1], 16;" :: "r"(dst), "l"(src));
}
__device__ __forceinline__ void cp_commit() {
    asm volatile("cp.async.commit_group;" ::: "memory");
}
template <int N>
__device__ __forceinline__ void cp_wait() {
    asm volatile("cp.async.wait_group %0;" :: "n"(N) : "memory");
}
// swizzled byte offset within a 128B-row tile, fp16 col c
__device__ __forceinline__ uint32_t swz_off(int row, int c) {
    return (uint32_t)(row * 128 + (((c >> 3) ^ (row & 7)) * 16) + (c & 7) * 2);
}

// =====================================================================
// Pre-split kernels
// =====================================================================
__global__ __launch_bounds__(256) void presplit_w(
    const float* __restrict__ kv_w, const float* __restrict__ q_w,
    const float* __restrict__ e_kv_w, const float* __restrict__ e_q_w)
{
    int id = blockIdx.x * 256 + threadIdx.x;
    if (id >= 1920 * 384 / 4) return;
    int idx4 = id * 4;
    int r = idx4 / 384, c = idx4 % 384;
    const float* src;
    if      (r < 768)  src = kv_w   + (size_t)r * 384 + c;
    else if (r < 1152) src = q_w    + (size_t)(r - 768) * 384 + c;
    else if (r < 1536) src = e_kv_w + (size_t)(r - 1152) * 384 + c;
    else               src = e_q_w  + (size_t)(r - 1536) * 384 + c;
    float4 v = *(const float4*)src;
    uint2 h, l; split4h(v, h, l);
    *(uint2*)&g_whi[idx4] = h;
    *(uint2*)&g_wlo[idx4] = l;
}

__global__ __launch_bounds__(256) void presplit_x(
    const float* __restrict__ x, const float* __restrict__ e)
{
    const int k = blockIdx.x, n = blockIdx.y, path = blockIdx.z;
    const float* src = (path ? e : x) + ((size_t)n * DIMC + k) * TV;
    size_t dst = ((size_t)(path * NB + n) * DIMC + k) * XPITCH;
    for (int l4 = threadIdx.x; l4 < XPITCH / 4; l4 += 256) {
        int f = l4 * 4;
        float4 v = (f < TV) ? *(const float4*)(src + f) : make_float4(0.f, 0.f, 0.f, 0.f);
        *(uint2*)&g_x16[dst + f] = cvt4h(v);
    }
}

// rpe (per-head 32x64, zero-padded) + proj_w (per-head 64x64) -> swizzled fp16 hi/lo
__global__ __launch_bounds__(256) void presplit_aux(
    const float* __restrict__ rpe, const float* __restrict__ proj_w, int nh)
{
    const int h = blockIdx.x;
    for (int idx = threadIdx.x; idx < 2048; idx += 256) {
        int row = idx >> 6, c = idx & 63;
        float val = (row < nh) ? rpe[(size_t)row * DIMC + h * 64 + c] : 0.f;
        __half hi = __float2half(val);
        __half lo = __float2half(val - __half2float(hi));
        uint32_t off = swz_off(row, c);
        *(__half*)(g_rhi_sw + h * 4096 + off) = hi;
        *(__half*)(g_rlo_sw + h * 4096 + off) = lo;
    }
    for (int idx = threadIdx.x; idx < 4096; idx += 256) {
        int row = idx >> 6, c = idx & 63;
        float val = proj_w[((size_t)h * 64 + row) * 64 + c];
        __half hi = __float2half(val);
        __half lo = __float2half(val - __half2float(hi));
        uint32_t off = swz_off(row, c);
        *(__half*)(g_pwhi_sw + h * 8192 + off) = hi;
        *(__half*)(g_pwlo_sw + h * 8192 + off) = lo;
    }
}

// =====================================================================
// Projection GEMM via mma.sync fp16 (W split hi/lo, X single; 2 MMAs/tile).
// CTA tile: M=128 x N=128, K=384, BK=32, 3-stage cp.async pipeline.
// Epilogue: smem transpose-stage -> fully coalesced float4 stores.
// =====================================================================
#define A_PITCH 80
#define B_PITCH 272
#define A_BYTES (128 * A_PITCH)
#define B_BYTES (32 * B_PITCH)
#define STAGE_BYTES (2 * A_BYTES + B_BYTES)      // 29184
#define DYN_BYTES (3 * STAGE_BYTES)              // 87552 >= 67584 epi stage

__global__ __launch_bounds__(256, 2)
void proj_mma()
{
    const int nt  = blockIdx.x;
    const int mt  = blockIdx.y;
    const int n   = blockIdx.z;
    const int tid = threadIdx.x;
    const int lane = tid & 31;
    const int w    = tid >> 5;
    const int wm   = w & 3;
    const int wn   = w >> 2;

    extern __shared__ char smem[];
    const uint32_t smem_b = smem_u32(smem);

    const int path = (mt >= 9);
    const int o_origin = (mt < 12) ? ((mt < 9) ? mt * 128 : (mt - 9) * 128)
                                   : (384 + (mt - 12) * 128);
    const int wrow0 = mt * 128;
    const int p0 = nt * 128;

    const __half* X16 = g_x16 + ((size_t)(path * NB + n) * DIMC) * XPITCH;

    const int a_row0 = (tid * 2) >> 2;
    const int a_s0   = (tid * 2) & 3;
    const int b_row0 = (tid * 2) >> 4;
    const int b_s0   = (tid * 2) & 15;

    const uint32_t aoff = (uint32_t)((wm * 32 + (lane & 15)) * A_PITCH + (lane >> 4) * 16);
    const uint32_t boff = (uint32_t)((lane & 15) * B_PITCH + (wn * 64 + (lane >> 4) * 8) * 2);

    float acc[16][4];
#pragma unroll
    for (int i = 0; i < 16; i++)
#pragma unroll
        for (int j = 0; j < 4; j++) acc[i][j] = 0.f;

    auto issue = [&](int c) {
        const int k0 = c * 32;
        const uint32_t st = smem_b + (uint32_t)((c % 3) * STAGE_BYTES);
#pragma unroll
        for (int i = 0; i < 2; i++) {
            int ar = a_row0;
            int as = (a_s0 + i) & 3;
            size_t asrc = (size_t)(wrow0 + ar) * 384 + k0 + as * 8;
            uint32_t adst = st + (uint32_t)(ar * A_PITCH + as * 16);
            cp16(adst, g_whi + asrc);
            cp16(adst + A_BYTES, g_wlo + asrc);
            int br = b_row0;
            int bs = (b_s0 + i) & 15;
            size_t bsrc = (size_t)(k0 + br) * XPITCH + p0 + bs * 8;
            uint32_t bdst = st + (uint32_t)(2 * A_BYTES + br * B_PITCH + bs * 16);
            cp16(bdst, X16 + bsrc);
        }
        cp_commit();
    };

    issue(0);
    issue(1);

    for (int c = 0; c < 12; ++c) {
        if (c < 11) cp_wait<1>(); else cp_wait<0>();
        __syncthreads();
        if (c < 10) issue(c + 2);

        const uint32_t stage = smem_b + (uint32_t)((c % 3) * STAGE_BYTES);
        const uint32_t aHi = stage + aoff;
        const uint32_t aLo = aHi + A_BYTES;
        const uint32_t bB  = stage + 2 * A_BYTES + boff;
#pragma unroll
        for (int s = 0; s < 2; s++) {
            uint32_t Ah[2][4], Al[2][4];
#pragma unroll
            for (int m = 0; m < 2; m++) {
                ldsm4(aHi + m * 16 * A_PITCH + s * 32, Ah[m]);
                ldsm4(aLo + m * 16 * A_PITCH + s * 32, Al[m]);
            }
            uint32_t Bh[4][4];
#pragma unroll
            for (int g = 0; g < 4; g++)
                ldsm4t(bB + s * 16 * B_PITCH + g * 32, Bh[g]);
#pragma unroll
            for (int m = 0; m < 2; m++)
#pragma unroll
                for (int g = 0; g < 4; g++)
#pragma unroll
                    for (int half = 0; half < 2; half++) {
                        float* cc = acc[m * 8 + g * 2 + half];
                        mma_f16(cc, Ah[m], &Bh[g][half * 2]);
                        mma_f16(cc, Al[m], &Bh[g][half * 2]);
                    }
        }
        __syncthreads();
    }

    // ---- epilogue: stage C into smem [p_local][o] (pitch 132, conflict-free),
    //      then fully coalesced float4 stores to g_proj ----
    float* stg = (float*)smem;
    const int g   = lane >> 2;
    const int tig = lane & 3;
#pragma unroll
    for (int m = 0; m < 2; m++) {
#pragma unroll
        for (int ntile = 0; ntile < 8; ntile++) {
#pragma unroll
            for (int j = 0; j < 4; j++) {
                int o  = wm * 32 + m * 16 + g + (j >> 1) * 8;
                int pl = wn * 64 + ntile * 8 + tig * 2 + (j & 1);
                stg[pl * 132 + o] = acc[m * 8 + ntile][j];
            }
        }
    }
    __syncthreads();

    const int slot = (o_origin / 384) + (path ? 3 : 0);
    const int hh0  = (o_origin % 384) >> 6;
    const size_t obase = (size_t)slot * SL + (size_t)n * NSTRIDE;
#pragma unroll
    for (int i = 0; i < 16; i++) {
        int f  = tid + 256 * i;          // 4096 float4s
        int pl = f >> 5;
        int o  = (f & 31) * 4;
        uint32_t p = (uint32_t)(p0 + pl);
        if (p < TV) {
            uint32_t t = (p * 5243u) >> 17;
            uint32_t v = p - t * 25u;
            uint32_t hh = (uint32_t)(hh0 + (o >> 6));
            uint32_t d  = (uint32_t)(o & 63);
            float* sp = &stg[pl * 132 + o];
            float4 val = make_float4(sp[0], sp[1], sp[2], sp[3]);
            *(float4*)&g_proj[obase + t * 9600u + hh * 1600u + v * 64u + d] = val;
        }
    }
}

// =====================================================================
// Kernel B: attention, tensor-core scores/qR/projection, fp16 2-MMA.
// One block (128 threads) per (n,t,h).
// =====================================================================
#define Q16_B  0
#define EQ16_B 4096
#define KEHI_B 8192
#define KELO_B 12288
#define EKHI_B 16384
#define EKLO_B 20480
#define RHI_B  24576
#define RLO_B  28672
#define XO16_B 0
#define PWHI_B 4096
#define PWLO_B 12288
#define OS_F   0
#define OD_F   700
#define OQR_F  1400

__global__ __launch_bounds__(128) void attn_kernel(
    const float* __restrict__ outer,
    const float* __restrict__ alpha_p, const float* __restrict__ beta_p,
    const float* __restrict__ proj_b,
    const int* __restrict__ hops, int nh,
    float* __restrict__ xo_out, float* __restrict__ eo_out)
{
    const int h = blockIdx.x, t = blockIdx.y, n = blockIdx.z;
    const int tid = threadIdx.x;
    const int lane = tid & 31;
    const int w = tid >> 5;

    __shared__ __align__(16) char smA[32768];
    __shared__ float sm[2100];
    __shared__ unsigned char shops[640];
    const uint32_t smA_u = smem_u32(smA);

    const size_t base = (((size_t)n * TT + t) * HH + h) * (size_t)(HD * VV);

    // ---- phase 0: zero pad rows of all 8 tiles + load/split + R + hops ----
    for (int z = tid; z < 448; z += 128) {
        int r = z >> 3, c = z & 7;
        int mtx = r / 7, row = 25 + (r % 7);
        *(float4*)(smA + mtx * 4096 + row * 128 + c * 16) =
            make_float4(0.f, 0.f, 0.f, 0.f);
    }
    for (int l4 = tid; l4 < 400; l4 += 128) {
        int f = l4 * 4;
        int v = f >> 6, d = f & 63;
        float4 k4  = *(const float4*)&g_proj[0 * (size_t)SL + base + f];
        float4 q4  = *(const float4*)&g_proj[2 * (size_t)SL + base + f];
        float4 ek4 = *(const float4*)&g_proj[3 * (size_t)SL + base + f];
        float4 eq4 = *(const float4*)&g_proj[4 * (size_t)SL + base + f];
        float4 ke4 = make_float4(k4.x + ek4.x, k4.y + ek4.y, k4.z + ek4.z, k4.w + ek4.w);
        uint32_t off = swz_off(v, d);
        *(uint2*)(smA + Q16_B  + off) = cvt4h(q4);
        *(uint2*)(smA + EQ16_B + off) = cvt4h(eq4);
        uint2 hh, ll;
        split4h(ke4, hh, ll);
        *(uint2*)(smA + KEHI_B + off) = hh; *(uint2*)(smA + KELO_B + off) = ll;
        split4h(ek4, hh, ll);
        *(uint2*)(smA + EKHI_B + off) = hh; *(uint2*)(smA + EKLO_B + off) = ll;
    }
    for (int i16 = tid; i16 < 256; i16 += 128) {
        *(uint4*)(smA + RHI_B + i16 * 16) = *(const uint4*)(g_rhi_sw + h * 4096 + i16 * 16);
        *(uint4*)(smA + RLO_B + i16 * 16) = *(const uint4*)(g_rlo_sw + h * 4096 + i16 * 16);
    }
    for (int l = tid; l < 625; l += 128) shops[l] = (unsigned char)hops[l];
    __syncthreads();

    // ---- phase 2: three GEMMs via mma (S1=Q.KE', G2=EQ.EK', QR=Q.R') ----
    {
        const int mt = w & 1;
        const int nb = (w >> 1) * 16;
        const int arow = mt * 16 + (lane & 15);
        const int brow = nb + (lane & 15);
        float accS[2][4], accD[2][4], accR[2][4];
#pragma unroll
        for (int i = 0; i < 2; i++)
#pragma unroll
            for (int j = 0; j < 4; j++) { accS[i][j] = 0.f; accD[i][j] = 0.f; accR[i][j] = 0.f; }

#pragma unroll
        for (int s = 0; s < 4; s++) {
            uint32_t abyte = (uint32_t)(arow * 128 + (((s * 2 + (lane >> 4)) ^ (arow & 7)) * 16));
            uint32_t bbyte = (uint32_t)(brow * 128 + (((s * 2 + (lane >> 4)) ^ (brow & 7)) * 16));
            uint32_t q[4], eq[4], keh[4], kel[4], ekh[4], ekl[4], rh[4], rl[4];
            ldsm4(smA_u + Q16_B  + abyte, q);
            ldsm4(smA_u + EQ16_B + abyte, eq);
            ldsm4(smA_u + KEHI_B + bbyte, keh);
            ldsm4(smA_u + KELO_B + bbyte, kel);
            ldsm4(smA_u + EKHI_B + bbyte, ekh);
            ldsm4(smA_u + EKLO_B + bbyte, ekl);
            ldsm4(smA_u + RHI_B  + bbyte, rh);
            ldsm4(smA_u + RLO_B  + bbyte, rl);
#pragma unroll
            for (int ns = 0; ns < 2; ns++) {
                uint32_t bKEh[2] = {keh[ns], keh[ns + 2]};
                uint32_t bKEl[2] = {kel[ns], kel[ns + 2]};
                uint32_t bEKh[2] = {ekh[ns], ekh[ns + 2]};
                uint32_t bEKl[2] = {ekl[ns], ekl[ns + 2]};
                uint32_t bRh[2]  = {rh[ns],  rh[ns + 2]};
                uint32_t bRl[2]  = {rl[ns],  rl[ns + 2]};
                mma_f16(accS[ns], q, bKEh);
                mma_f16(accS[ns], q, bKEl);
                mma_f16(accD[ns], eq, bEKh);
                mma_f16(accD[ns], eq, bEKl);
                mma_f16(accR[ns], q, bRh);
                mma_f16(accR[ns], q, bRl);
            }
        }
#pragma unroll
        for (int ns = 0; ns < 2; ns++) {
#pragma unroll
            for (int j = 0; j < 4; j++) {
                int row = mt * 16 + (lane >> 2) + (j >> 1) * 8;
                int col = nb + ns * 8 + (lane & 3) * 2 + (j & 1);
                if (row < 25 && col < nh)
                    sm[OQR_F + row * 28 + col] = accR[ns][j];
            }
        }
        __syncthreads();
#pragma unroll
        for (int ns = 0; ns < 2; ns++) {
#pragma unroll
            for (int j = 0; j < 4; j++) {
                int row = mt * 16 + (lane >> 2) + (j >> 1) * 8;
                int col = nb + ns * 8 + (lane & 3) * 2 + (j & 1);
                if (row < 25 && col < 25) {
                    float g2 = accD[ns][j];
                    float b = sm[OQR_F + row * 28 + shops[row * 25 + col]];
                    sm[OS_F + row * 28 + col] = accS[ns][j] + g2 + b;
                    sm[OD_F + row * 28 + col] = g2;
                }
            }
        }
    }
    __syncthreads();

    const float alpha = __ldg(alpha_p);
    const float beta  = __ldg(beta_p);
    const float scale = 0.125f;

    // ---- phase 3: softmax (50 rows), fold alpha/outer/beta ----
    if (tid < 50) {
        int i = tid % 25;
        float* row = &sm[(tid < 25 ? OS_F : OD_F) + i * 28];
        float m = -1e30f;
#pragma unroll
        for (int j = 0; j < 25; j++) m = fmaxf(m, row[j]);
        float ebuf[25];
        float s = 0.f;
#pragma unroll
        for (int j = 0; j < 25; j++) { float v = expf((row[j] - m) * scale); ebuf[j] = v; s += v; }
        float inv = 1.f / s;
        if (tid < 25) {
            const float* orow = outer + (size_t)h * 625 + i * 25;
#pragma unroll
            for (int j = 0; j < 25; j++)
                row[j] = alpha * (ebuf[j] * inv) + __ldg(orow + j);
        } else {
#pragma unroll
            for (int j = 0; j < 25; j++)
                row[j] = beta * (ebuf[j] * inv);
        }
    }
    __syncthreads();

    // ---- phase 4: AV (V from gmem); XO -> fp16 smem; load PW tiles ----
    for (int z = tid; z < 56; z += 128) {
        int r = 25 + (z >> 3), c = z & 7;
        *(float4*)(smA + XO16_B + r * 128 + c * 16) = make_float4(0.f, 0.f, 0.f, 0.f);
    }
    for (int i16 = tid; i16 < 512; i16 += 128) {
        *(uint4*)(smA + PWHI_B + i16 * 16) = *(const uint4*)(g_pwhi_sw + h * 8192 + i16 * 16);
        *(uint4*)(smA + PWLO_B + i16 * 16) = *(const uint4*)(g_pwlo_sw + h * 8192 + i16 * 16);
    }
    if (tid < 80) {
        int ig = tid / 16;
        int dg = tid % 16;
        float aX[5][4], aE[5][4];
#pragma unroll
        for (int ii = 0; ii < 5; ii++)
#pragma unroll
            for (int dd = 0; dd < 4; dd++) { aX[ii][dd] = 0.f; aE[ii][dd] = 0.f; }
#pragma unroll
        for (int j = 0; j < 25; j++) {
            float4 v4 = __ldg((const float4*)&g_proj[1 * (size_t)SL + base + j * 64 + dg * 4]);
#pragma unroll
            for (int ii = 0; ii < 5; ii++) {
                float a  = sm[OS_F + (ig * 5 + ii) * 28 + j];
                float dc = sm[OD_F + (ig * 5 + ii) * 28 + j];
                aX[ii][0] += a * v4.x;  aX[ii][1] += a * v4.y;
                aX[ii][2] += a * v4.z;  aX[ii][3] += a * v4.w;
                aE[ii][0] += dc * v4.x; aE[ii][1] += dc * v4.y;
                aE[ii][2] += dc * v4.z; aE[ii][3] += dc * v4.w;
            }
        }
        const int d0 = dg * 4;
#pragma unroll
        for (int ii = 0; ii < 5; ii++) {
            int i = ig * 5 + ii;
#pragma unroll
            for (int dd = 0; dd < 4; dd++)
                eo_out[(((size_t)n * DIMC + h * HD + d0 + dd) * TT + t) * VV + i] = aE[ii][dd];
            float4 xv = make_float4(aX[ii][0], aX[ii][1], aX[ii][2], aX[ii][3]);
            *(uint2*)(smA + XO16_B + swz_off(i, d0)) = cvt4h(xv);
        }
    }
    __syncthreads();

    // ---- phase 5: grouped projection via mma: OUT(25x64) = XO(25x64).W'(64x64) ----
    {
        const int mt = w & 1;
        const int ng = w >> 1;
        const int arow = mt * 16 + (lane & 15);
        float accP[2][2][4];
#pragma unroll
        for (int a = 0; a < 2; a++)
#pragma unroll
            for (int b = 0; b < 2; b++)
#pragma unroll
                for (int j = 0; j < 4; j++) accP[a][b][j] = 0.f;

#pragma unroll
        for (int s = 0; s < 4; s++) {
            uint32_t abyte = (uint32_t)(arow * 128 + (((s * 2 + (lane >> 4)) ^ (arow & 7)) * 16));
            uint32_t xh[4];
            ldsm4(smA_u + XO16_B + abyte, xh);
#pragma unroll
            for (int nt2 = 0; nt2 < 2; nt2++) {
                int brow = (ng * 2 + nt2) * 16 + (lane & 15);
                uint32_t bbyte = (uint32_t)(brow * 128 + (((s * 2 + (lane >> 4)) ^ (brow & 7)) * 16));
                uint32_t wh[4], wl[4];
                ldsm4(smA_u + PWHI_B + bbyte, wh);
                ldsm4(smA_u + PWLO_B + bbyte, wl);
#pragma unroll
                for (int ns = 0; ns < 2; ns++) {
                    uint32_t bh[2] = {wh[ns], wh[ns + 2]};
                    uint32_t bl[2] = {wl[ns], wl[ns + 2]};
                    mma_f16(accP[nt2][ns], xh, bh);
                    mma_f16(accP[nt2][ns], xh, bl);
                }
            }
        }
#pragma unroll
        for (int nt2 = 0; nt2 < 2; nt2++) {
#pragma unroll
            for (int ns = 0; ns < 2; ns++) {
#pragma unroll
                for (int j = 0; j < 4; j++) {
                    int row = mt * 16 + (lane >> 2) + (j >> 1) * 8;
                    int col = (ng * 2 + nt2) * 16 + ns * 8 + (lane & 3) * 2 + (j & 1);
                    if (row < 25) {
                        float b = __ldg(proj_b + h * HD + col);
                        xo_out[(((size_t)n * DIMC + h * HD + col) * TT + t) * VV + row] =
                            accP[nt2][ns][j] + b;
                    }
                }
            }
        }
    }
}

extern "C" void kernel_launch(void* const* d_in, const int* in_sizes, int n_in,
                              void* d_out, int out_size)
{
    const float* x      = (const float*)d_in[0];
    const float* e      = (const float*)d_in[1];
    const float* kv_w   = (const float*)d_in[2];
    const float* q_w    = (const float*)d_in[3];
    const float* e_kv_w = (const float*)d_in[4];
    const float* e_q_w  = (const float*)d_in[5];
    const float* rpe    = (const float*)d_in[6];
    const float* outerp = (const float*)d_in[7];
    const float* alpha  = (const float*)d_in[8];
    const float* beta   = (const float*)d_in[9];
    const float* proj_w = (const float*)d_in[10];
    const float* proj_b = (const float*)d_in[11];
    const int*   hops   = (const int*)d_in[12];

    int nh = in_sizes[6] / DIMC;

    float* xo = (float*)d_out;
    float* eo = xo + (size_t)NB * DIMC * TT * VV;

    presplit_w<<<(1920 * 384 / 4 + 255) / 256, 256>>>(kv_w, q_w, e_kv_w, e_q_w);
    presplit_x<<<dim3(DIMC, NB, 2), 256>>>(x, e);
    presplit_aux<<<6, 256>>>(rpe, proj_w, nh);

    cudaFuncSetAttribute(proj_mma, cudaFuncAttributeMaxDynamicSharedMemorySize, DYN_BYTES);
    proj_mma<<<dim3(13, 15, NB), 256, DYN_BYTES>>>();
    attn_kernel<<<dim3(HH, TT, NB), 128>>>(outerp, alpha, beta,
                                           proj_b, hops, nh, xo, eo);
}

// round 16
// speedup vs baseline: 2.6330x; 1.4315x over previous
#include <cuda_runtime.h>
#include <cuda_fp16.h>
#include <math.h>
#include <stdint.h>

#define NB   64
#define TT   64
#define VV   25
#define DIMC 384
#define HH   6
#define HD   64
#define TV   1600                 // T*V
#define SL   39321600             // N*T*H*HD*V  (per-slot scratch size)
#define NSTRIDE 614400u           // T*H*HD*V    (per-n stride within a slot)
#define XPITCH 1664               // padded TV for cp.async (multiple of 128)

// Scratch: slots 0..4 = K, V, Q, EK, EQ, each [N,T,H,V,HD] fp32 (v-major inner)
__device__ float g_proj[5u * SL];
// Pre-converted GEMM operands (single fp16)
__device__ __half g_w16[1920 * 384];
__device__ __half g_x16[2u * NB * DIMC * XPITCH];
// Pre-converted, pre-swizzled per-head aux tiles (rpe 32x64, proj_w 64x64)
__device__ __align__(16) char g_r_sw[6 * 4096];
__device__ __align__(16) char g_pw_sw[6 * 8192];

// ---------------- helpers ----------------
__device__ __forceinline__ uint32_t smem_u32(const void* p) {
    uint32_t a;
    asm("{ .reg .u64 t; cvta.to.shared.u64 t, %1; cvt.u32.u64 %0, t; }"
        : "=r"(a) : "l"(p));
    return a;
}
__device__ __forceinline__ uint2 cvt4h(float4 v) {
    __half2 h0 = __floats2half2_rn(v.x, v.y);
    __half2 h1 = __floats2half2_rn(v.z, v.w);
    return make_uint2(*(uint32_t*)&h0, *(uint32_t*)&h1);
}
__device__ __forceinline__ void ldsm4(uint32_t addr, uint32_t* r) {
    asm volatile("ldmatrix.sync.aligned.m8n8.x4.shared.b16 {%0,%1,%2,%3}, [%4];"
                 : "=r"(r[0]), "=r"(r[1]), "=r"(r[2]), "=r"(r[3]) : "r"(addr));
}
__device__ __forceinline__ void ldsm4t(uint32_t addr, uint32_t* r) {
    asm volatile("ldmatrix.sync.aligned.m8n8.x4.trans.shared.b16 {%0,%1,%2,%3}, [%4];"
                 : "=r"(r[0]), "=r"(r[1]), "=r"(r[2]), "=r"(r[3]) : "r"(addr));
}
__device__ __forceinline__ void mma_f16(float* c, const uint32_t* a, const uint32_t* b) {
    asm volatile("mma.sync.aligned.m16n8k16.row.col.f32.f16.f16.f32 "
                 "{%0,%1,%2,%3}, {%4,%5,%6,%7}, {%8,%9}, {%0,%1,%2,%3};"
                 : "+f"(c[0]), "+f"(c[1]), "+f"(c[2]), "+f"(c[3])
                 : "r"(a[0]), "r"(a[1]), "r"(a[2]), "r"(a[3]), "r"(b[0]), "r"(b[1]));
}
__device__ __forceinline__ void cp16(uint32_t dst, const void* src) {
    asm volatile("cp.async.cg.shared.global [%0], [%1], 16;" :: "r"(dst), "l"(src));
}
__device__ __forceinline__ void cp_commit() {
    asm volatile("cp.async.commit_group;" ::: "memory");
}
template <int N>
__device__ __forceinline__ void cp_wait() {
    asm volatile("cp.async.wait_group %0;" :: "n"(N) : "memory");
}
// swizzled byte offset within a 128B-row tile, fp16 col c
__device__ __forceinline__ uint32_t swz_off(int row, int c) {
    return (uint32_t)(row * 128 + (((c >> 3) ^ (row & 7)) * 16) + (c & 7) * 2);
}

// =====================================================================
// Pre-convert kernels (fp32 -> fp16)
// =====================================================================
__global__ __launch_bounds__(256) void presplit_w(
    const float* __restrict__ kv_w, const float* __restrict__ q_w,
    const float* __restrict__ e_kv_w, const float* __restrict__ e_q_w)
{
    int id = blockIdx.x * 256 + threadIdx.x;
    if (id >= 1920 * 384 / 4) return;
    int idx4 = id * 4;
    int r = idx4 / 384, c = idx4 % 384;
    const float* src;
    if      (r < 768)  src = kv_w   + (size_t)r * 384 + c;
    else if (r < 1152) src = q_w    + (size_t)(r - 768) * 384 + c;
    else if (r < 1536) src = e_kv_w + (size_t)(r - 1152) * 384 + c;
    else               src = e_q_w  + (size_t)(r - 1536) * 384 + c;
    *(uint2*)&g_w16[idx4] = cvt4h(*(const float4*)src);
}

__global__ __launch_bounds__(256) void presplit_x(
    const float* __restrict__ x, const float* __restrict__ e)
{
    const int k = blockIdx.x, n = blockIdx.y, path = blockIdx.z;
    const float* src = (path ? e : x) + ((size_t)n * DIMC + k) * TV;
    size_t dst = ((size_t)(path * NB + n) * DIMC + k) * XPITCH;
    for (int l4 = threadIdx.x; l4 < XPITCH / 4; l4 += 256) {
        int f = l4 * 4;
        float4 v = (f < TV) ? *(const float4*)(src + f) : make_float4(0.f, 0.f, 0.f, 0.f);
        *(uint2*)&g_x16[dst + f] = cvt4h(v);
    }
}

// rpe (per-head 32x64, zero-padded) + proj_w (per-head 64x64) -> swizzled fp16
__global__ __launch_bounds__(256) void presplit_aux(
    const float* __restrict__ rpe, const float* __restrict__ proj_w, int nh)
{
    const int h = blockIdx.x;
    for (int idx = threadIdx.x; idx < 2048; idx += 256) {
        int row = idx >> 6, c = idx & 63;
        float val = (row < nh) ? rpe[(size_t)row * DIMC + h * 64 + c] : 0.f;
        *(__half*)(g_r_sw + h * 4096 + swz_off(row, c)) = __float2half(val);
    }
    for (int idx = threadIdx.x; idx < 4096; idx += 256) {
        int row = idx >> 6, c = idx & 63;
        float val = proj_w[((size_t)h * 64 + row) * 64 + c];
        *(__half*)(g_pw_sw + h * 8192 + swz_off(row, c)) = __float2half(val);
    }
}

// =====================================================================
// Projection GEMM via mma.sync fp16 (single MMA per tile).
// CTA tile: M=128 x N=128, K=384, BK=32, 3-stage cp.async pipeline.
// Epilogue: smem transpose-stage -> fully coalesced float4 stores.
// =====================================================================
#define A_PITCH 80
#define B_PITCH 272
#define A_BYTES (128 * A_PITCH)                  // 10240
#define B_BYTES (32 * B_PITCH)                   // 8704
#define STAGE_BYTES (A_BYTES + B_BYTES)          // 18944
#define DYN_BYTES 67584                          // max(3*STAGE, 128*132*4 epi stage)

__global__ __launch_bounds__(256, 2)
void proj_mma()
{
    const int nt  = blockIdx.x;
    const int mt  = blockIdx.y;
    const int n   = blockIdx.z;
    const int tid = threadIdx.x;
    const int lane = tid & 31;
    const int w    = tid >> 5;
    const int wm   = w & 3;
    const int wn   = w >> 2;

    extern __shared__ char smem[];
    const uint32_t smem_b = smem_u32(smem);

    const int path = (mt >= 9);
    const int o_origin = (mt < 12) ? ((mt < 9) ? mt * 128 : (mt - 9) * 128)
                                   : (384 + (mt - 12) * 128);
    const int wrow0 = mt * 128;
    const int p0 = nt * 128;

    const __half* X16 = g_x16 + ((size_t)(path * NB + n) * DIMC) * XPITCH;

    const int a_row0 = (tid * 2) >> 2;
    const int a_s0   = (tid * 2) & 3;
    const int b_row0 = (tid * 2) >> 4;
    const int b_s0   = (tid * 2) & 15;

    const uint32_t aoff = (uint32_t)((wm * 32 + (lane & 15)) * A_PITCH + (lane >> 4) * 16);
    const uint32_t boff = (uint32_t)((lane & 15) * B_PITCH + (wn * 64 + (lane >> 4) * 8) * 2);

    float acc[16][4];
#pragma unroll
    for (int i = 0; i < 16; i++)
#pragma unroll
        for (int j = 0; j < 4; j++) acc[i][j] = 0.f;

    auto issue = [&](int c) {
        const int k0 = c * 32;
        const uint32_t st = smem_b + (uint32_t)((c % 3) * STAGE_BYTES);
#pragma unroll
        for (int i = 0; i < 2; i++) {
            int as = (a_s0 + i) & 3;
            size_t asrc = (size_t)(wrow0 + a_row0) * 384 + k0 + as * 8;
            cp16(st + (uint32_t)(a_row0 * A_PITCH + as * 16), g_w16 + asrc);
            int bs = (b_s0 + i) & 15;
            size_t bsrc = (size_t)(k0 + b_row0) * XPITCH + p0 + bs * 8;
            cp16(st + (uint32_t)(A_BYTES + b_row0 * B_PITCH + bs * 16), X16 + bsrc);
        }
        cp_commit();
    };

    issue(0);
    issue(1);

    for (int c = 0; c < 12; ++c) {
        if (c < 11) cp_wait<1>(); else cp_wait<0>();
        __syncthreads();
        if (c < 10) issue(c + 2);

        const uint32_t stage = smem_b + (uint32_t)((c % 3) * STAGE_BYTES);
        const uint32_t aA = stage + aoff;
        const uint32_t bB = stage + A_BYTES + boff;
#pragma unroll
        for (int s = 0; s < 2; s++) {
            uint32_t Ah[2][4];
#pragma unroll
            for (int m = 0; m < 2; m++)
                ldsm4(aA + m * 16 * A_PITCH + s * 32, Ah[m]);
            uint32_t Bh[4][4];
#pragma unroll
            for (int g = 0; g < 4; g++)
                ldsm4t(bB + s * 16 * B_PITCH + g * 32, Bh[g]);
#pragma unroll
            for (int m = 0; m < 2; m++)
#pragma unroll
                for (int g = 0; g < 4; g++)
#pragma unroll
                    for (int half = 0; half < 2; half++)
                        mma_f16(acc[m * 8 + g * 2 + half], Ah[m], &Bh[g][half * 2]);
        }
        __syncthreads();
    }

    // ---- epilogue: stage C into smem [p_local][o] (pitch 132), coalesced stores ----
    float* stg = (float*)smem;
    const int g   = lane >> 2;
    const int tig = lane & 3;
#pragma unroll
    for (int m = 0; m < 2; m++) {
#pragma unroll
        for (int ntile = 0; ntile < 8; ntile++) {
#pragma unroll
            for (int j = 0; j < 4; j++) {
                int o  = wm * 32 + m * 16 + g + (j >> 1) * 8;
                int pl = wn * 64 + ntile * 8 + tig * 2 + (j & 1);
                stg[pl * 132 + o] = acc[m * 8 + ntile][j];
            }
        }
    }
    __syncthreads();

    const int slot = (o_origin / 384) + (path ? 3 : 0);
    const int hh0  = (o_origin % 384) >> 6;
    const size_t obase = (size_t)slot * SL + (size_t)n * NSTRIDE;
#pragma unroll
    for (int i = 0; i < 16; i++) {
        int f  = tid + 256 * i;          // 4096 float4s
        int pl = f >> 5;
        int o  = (f & 31) * 4;
        uint32_t p = (uint32_t)(p0 + pl);
        if (p < TV) {
            uint32_t t = (p * 5243u) >> 17;
            uint32_t v = p - t * 25u;
            uint32_t hh = (uint32_t)(hh0 + (o >> 6));
            uint32_t d  = (uint32_t)(o & 63);
            float* sp = &stg[pl * 132 + o];
            float4 val = make_float4(sp[0], sp[1], sp[2], sp[3]);
            *(float4*)&g_proj[obase + t * 9600u + hh * 1600u + v * 64u + d] = val;
        }
    }
}

// =====================================================================
// Kernel B: attention, tensor-core scores/qR/projection, single fp16 MMA.
// One block (128 threads) per (n,t,h).
// smA: 5 swizzled 32x128B fp16 tiles (Q,EQ,KE,EK,R);
//   phase 4-5 reuse: XO16 0, PW16 4096.
// =====================================================================
#define Q16_B  0
#define EQ16_B 4096
#define KE16_B 8192
#define EK16_B 12288
#define R16_B  16384
#define XO16_B 0
#define PW16_B 4096
#define OS_F   0
#define OD_F   700
#define OQR_F  1400

__global__ __launch_bounds__(128) void attn_kernel(
    const float* __restrict__ outer,
    const float* __restrict__ alpha_p, const float* __restrict__ beta_p,
    const float* __restrict__ proj_b,
    const int* __restrict__ hops, int nh,
    float* __restrict__ xo_out, float* __restrict__ eo_out)
{
    const int h = blockIdx.x, t = blockIdx.y, n = blockIdx.z;
    const int tid = threadIdx.x;
    const int lane = tid & 31;
    const int w = tid >> 5;

    __shared__ __align__(16) char smA[20480];
    __shared__ float sm[2100];
    __shared__ unsigned char shops[640];
    const uint32_t smA_u = smem_u32(smA);

    const size_t base = (((size_t)n * TT + t) * HH + h) * (size_t)(HD * VV);

    // ---- phase 0: zero pad rows (25..31) of Q/EQ/KE/EK + load/convert + R + hops ----
    for (int z = tid; z < 224; z += 128) {
        int r = z >> 3, c = z & 7;
        int mtx = r / 7, row = 25 + (r % 7);
        *(float4*)(smA + mtx * 4096 + row * 128 + c * 16) =
            make_float4(0.f, 0.f, 0.f, 0.f);
    }
    for (int l4 = tid; l4 < 400; l4 += 128) {
        int f = l4 * 4;
        int v = f >> 6, d = f & 63;
        float4 k4  = *(const float4*)&g_proj[0 * (size_t)SL + base + f];
        float4 q4  = *(const float4*)&g_proj[2 * (size_t)SL + base + f];
        float4 ek4 = *(const float4*)&g_proj[3 * (size_t)SL + base + f];
        float4 eq4 = *(const float4*)&g_proj[4 * (size_t)SL + base + f];
        float4 ke4 = make_float4(k4.x + ek4.x, k4.y + ek4.y, k4.z + ek4.z, k4.w + ek4.w);
        uint32_t off = swz_off(v, d);
        *(uint2*)(smA + Q16_B  + off) = cvt4h(q4);
        *(uint2*)(smA + EQ16_B + off) = cvt4h(eq4);
        *(uint2*)(smA + KE16_B + off) = cvt4h(ke4);
        *(uint2*)(smA + EK16_B + off) = cvt4h(ek4);
    }
    for (int i16 = tid; i16 < 256; i16 += 128)
        *(uint4*)(smA + R16_B + i16 * 16) = *(const uint4*)(g_r_sw + h * 4096 + i16 * 16);
    for (int l = tid; l < 625; l += 128) shops[l] = (unsigned char)hops[l];
    __syncthreads();

    // ---- phase 2: three GEMMs via mma (S1=Q.KE', G2=EQ.EK', QR=Q.R') ----
    {
        const int mt = w & 1;
        const int nb = (w >> 1) * 16;
        const int arow = mt * 16 + (lane & 15);
        const int brow = nb + (lane & 15);
        float accS[2][4], accD[2][4], accR[2][4];
#pragma unroll
        for (int i = 0; i < 2; i++)
#pragma unroll
            for (int j = 0; j < 4; j++) { accS[i][j] = 0.f; accD[i][j] = 0.f; accR[i][j] = 0.f; }

#pragma unroll
        for (int s = 0; s < 4; s++) {
            uint32_t abyte = (uint32_t)(arow * 128 + (((s * 2 + (lane >> 4)) ^ (arow & 7)) * 16));
            uint32_t bbyte = (uint32_t)(brow * 128 + (((s * 2 + (lane >> 4)) ^ (brow & 7)) * 16));
            uint32_t q[4], eq[4], ke[4], ek[4], r[4];
            ldsm4(smA_u + Q16_B  + abyte, q);
            ldsm4(smA_u + EQ16_B + abyte, eq);
            ldsm4(smA_u + KE16_B + bbyte, ke);
            ldsm4(smA_u + EK16_B + bbyte, ek);
            ldsm4(smA_u + R16_B  + bbyte, r);
#pragma unroll
            for (int ns = 0; ns < 2; ns++) {
                uint32_t bKE[2] = {ke[ns], ke[ns + 2]};
                uint32_t bEK[2] = {ek[ns], ek[ns + 2]};
                uint32_t bR[2]  = {r[ns],  r[ns + 2]};
                mma_f16(accS[ns], q, bKE);
                mma_f16(accD[ns], eq, bEK);
                mma_f16(accR[ns], q, bR);
            }
        }
#pragma unroll
        for (int ns = 0; ns < 2; ns++) {
#pragma unroll
            for (int j = 0; j < 4; j++) {
                int row = mt * 16 + (lane >> 2) + (j >> 1) * 8;
                int col = nb + ns * 8 + (lane & 3) * 2 + (j & 1);
                if (row < 25 && col < nh)
                    sm[OQR_F + row * 28 + col] = accR[ns][j];
            }
        }
        __syncthreads();
#pragma unroll
        for (int ns = 0; ns < 2; ns++) {
#pragma unroll
            for (int j = 0; j < 4; j++) {
                int row = mt * 16 + (lane >> 2) + (j >> 1) * 8;
                int col = nb + ns * 8 + (lane & 3) * 2 + (j & 1);
                if (row < 25 && col < 25) {
                    float g2 = accD[ns][j];
                    float b = sm[OQR_F + row * 28 + shops[row * 25 + col]];
                    sm[OS_F + row * 28 + col] = accS[ns][j] + g2 + b;
                    sm[OD_F + row * 28 + col] = g2;
                }
            }
        }
    }
    __syncthreads();

    const float alpha = __ldg(alpha_p);
    const float beta  = __ldg(beta_p);
    const float scale = 0.125f;

    // ---- phase 3: softmax (50 rows), fold alpha/outer/beta ----
    if (tid < 50) {
        int i = tid % 25;
        float* row = &sm[(tid < 25 ? OS_F : OD_F) + i * 28];
        float m = -1e30f;
#pragma unroll
        for (int j = 0; j < 25; j++) m = fmaxf(m, row[j]);
        float ebuf[25];
        float s = 0.f;
#pragma unroll
        for (int j = 0; j < 25; j++) { float v = expf((row[j] - m) * scale); ebuf[j] = v; s += v; }
        float inv = 1.f / s;
        if (tid < 25) {
            const float* orow = outer + (size_t)h * 625 + i * 25;
#pragma unroll
            for (int j = 0; j < 25; j++)
                row[j] = alpha * (ebuf[j] * inv) + __ldg(orow + j);
        } else {
#pragma unroll
            for (int j = 0; j < 25; j++)
                row[j] = beta * (ebuf[j] * inv);
        }
    }
    __syncthreads();

    // ---- phase 4: AV (V from gmem); XO -> fp16 smem; load PW tile ----
    for (int z = tid; z < 56; z += 128) {
        int r = 25 + (z >> 3), c = z & 7;
        *(float4*)(smA + XO16_B + r * 128 + c * 16) = make_float4(0.f, 0.f, 0.f, 0.f);
    }
    for (int i16 = tid; i16 < 512; i16 += 128)
        *(uint4*)(smA + PW16_B + i16 * 16) = *(const uint4*)(g_pw_sw + h * 8192 + i16 * 16);
    if (tid < 80) {
        int ig = tid / 16;
        int dg = tid % 16;
        float aX[5][4], aE[5][4];
#pragma unroll
        for (int ii = 0; ii < 5; ii++)
#pragma unroll
            for (int dd = 0; dd < 4; dd++) { aX[ii][dd] = 0.f; aE[ii][dd] = 0.f; }
#pragma unroll
        for (int j = 0; j < 25; j++) {
            float4 v4 = __ldg((const float4*)&g_proj[1 * (size_t)SL + base + j * 64 + dg * 4]);
#pragma unroll
            for (int ii = 0; ii < 5; ii++) {
                float a  = sm[OS_F + (ig * 5 + ii) * 28 + j];
                float dc = sm[OD_F + (ig * 5 + ii) * 28 + j];
                aX[ii][0] += a * v4.x;  aX[ii][1] += a * v4.y;
                aX[ii][2] += a * v4.z;  aX[ii][3] += a * v4.w;
                aE[ii][0] += dc * v4.x; aE[ii][1] += dc * v4.y;
                aE[ii][2] += dc * v4.z; aE[ii][3] += dc * v4.w;
            }
        }
        const int d0 = dg * 4;
#pragma unroll
        for (int ii = 0; ii < 5; ii++) {
            int i = ig * 5 + ii;
#pragma unroll
            for (int dd = 0; dd < 4; dd++)
                eo_out[(((size_t)n * DIMC + h * HD + d0 + dd) * TT + t) * VV + i] = aE[ii][dd];
            float4 xv = make_float4(aX[ii][0], aX[ii][1], aX[ii][2], aX[ii][3]);
            *(uint2*)(smA + XO16_B + swz_off(i, d0)) = cvt4h(xv);
        }
    }
    __syncthreads();

    // ---- phase 5: grouped projection via mma: OUT(25x64) = XO(25x64).W'(64x64) ----
    {
        const int mt = w & 1;
        const int ng = w >> 1;
        const int arow = mt * 16 + (lane & 15);
        float accP[2][2][4];
#pragma unroll
        for (int a = 0; a < 2; a++)
#pragma unroll
            for (int b = 0; b < 2; b++)
#pragma unroll
                for (int j = 0; j < 4; j++) accP[a][b][j] = 0.f;

#pragma unroll
        for (int s = 0; s < 4; s++) {
            uint32_t abyte = (uint32_t)(arow * 128 + (((s * 2 + (lane >> 4)) ^ (arow & 7)) * 16));
            uint32_t xh[4];
            ldsm4(smA_u + XO16_B + abyte, xh);
#pragma unroll
            for (int nt2 = 0; nt2 < 2; nt2++) {
                int brow = (ng * 2 + nt2) * 16 + (lane & 15);
                uint32_t bbyte = (uint32_t)(brow * 128 + (((s * 2 + (lane >> 4)) ^ (brow & 7)) * 16));
                uint32_t wh[4];
                ldsm4(smA_u + PW16_B + bbyte, wh);
#pragma unroll
                for (int ns = 0; ns < 2; ns++) {
                    uint32_t bh[2] = {wh[ns], wh[ns + 2]};
                    mma_f16(accP[nt2][ns], xh, bh);
                }
            }
        }
#pragma unroll
        for (int nt2 = 0; nt2 < 2; nt2++) {
#pragma unroll
            for (int ns = 0; ns < 2; ns++) {
#pragma unroll
                for (int j = 0; j < 4; j++) {
                    int row = mt * 16 + (lane >> 2) + (j >> 1) * 8;
                    int col = (ng * 2 + nt2) * 16 + ns * 8 + (lane & 3) * 2 + (j & 1);
                    if (row < 25) {
                        float b = __ldg(proj_b + h * HD + col);
                        xo_out[(((size_t)n * DIMC + h * HD + col) * TT + t) * VV + row] =
                            accP[nt2][ns][j] + b;
                    }
                }
            }
        }
    }
}

extern "C" void kernel_launch(void* const* d_in, const int* in_sizes, int n_in,
                              void* d_out, int out_size)
{
    const float* x      = (const float*)d_in[0];
    const float* e      = (const float*)d_in[1];
    const float* kv_w   = (const float*)d_in[2];
    const float* q_w    = (const float*)d_in[3];
    const float* e_kv_w = (const float*)d_in[4];
    const float* e_q_w  = (const float*)d_in[5];
    const float* rpe    = (const float*)d_in[6];
    const float* outerp = (const float*)d_in[7];
    const float* alpha  = (const float*)d_in[8];
    const float* beta   = (const float*)d_in[9];
    const float* proj_w = (const float*)d_in[10];
    const float* proj_b = (const float*)d_in[11];
    const int*   hops   = (const int*)d_in[12];

    int nh = in_sizes[6] / DIMC;

    float* xo = (float*)d_out;
    float* eo = xo + (size_t)NB * DIMC * TT * VV;

    presplit_w<<<(1920 * 384 / 4 + 255) / 256, 256>>>(kv_w, q_w, e_kv_w, e_q_w);
    presplit_x<<<dim3(DIMC, NB, 2), 256>>>(x, e);
    presplit_aux<<<6, 256>>>(rpe, proj_w, nh);

    cudaFuncSetAttribute(proj_mma, cudaFuncAttributeMaxDynamicSharedMemorySize, DYN_BYTES);
    proj_mma<<<dim3(13, 15, NB), 256, DYN_BYTES>>>();
    attn_kernel<<<dim3(HH, TT, NB), 128>>>(outerp, alpha, beta,
                                           proj_b, hops, nh, xo, eo);
}